// round 7
// baseline (speedup 1.0000x reference)
#include <cuda_runtime.h>
#include <cuda_bf16.h>
#include <cstdint>
#include <math_constants.h>

#define Bb 2
#define Ll 256
#define Ee 512
#define Hh 8
#define QSCALE 0.125f

// ---------------- device scratch ----------------
__device__ float g_q[Bb*Ll*Ee];
__device__ float g_k[Bb*Ll*Ee];
__device__ float g_v[Bb*Ll*Ee];
__device__ float g_logits[(size_t)Bb*Hh*Ll*Ll];
__device__ float g_w[(size_t)Bb*Hh*Ll*Ll];
__device__ float g_o1[Bb*Ll*Ee];
// compacted (list-ordered) bf16 hi/lo splits of unmasked relation rows
__device__ __nv_bfloat16 g_rel_hi[(size_t)Bb*Ll*Ll*Ee];
__device__ __nv_bfloat16 g_rel_lo[(size_t)Bb*Ll*Ll*Ee];
__device__ __nv_bfloat16 g_w_hi[1024*512];  // [h*128+p][k]; p<64: Wrq rows, p>=64: Wrk rows
__device__ __nv_bfloat16 g_w_lo[1024*512];
__device__ int g_cnt[Bb];
__device__ unsigned short g_list[Bb*Ll*Ll];   // packed (j<<8)|i of unmasked pairs

// ==================== PTX helpers (sm_103 baseline only) ====================
__device__ __forceinline__ uint32_t smem_u32(const void* p) {
    uint32_t a;
    asm("{ .reg .u64 t; cvta.to.shared.u64 t, %1; cvt.u32.u64 %0, t; }" : "=r"(a) : "l"(p));
    return a;
}
#define SMEM_SWZ(o) ((o) ^ (((o) >> 3) & 0x70))
#define CP_ASYNC16(dst, src) \
    asm volatile("cp.async.cg.shared.global [%0], [%1], 16;" :: "r"(dst), "l"(src))
#define CP_COMMIT() asm volatile("cp.async.commit_group;" ::: "memory")
#define CP_WAIT1() asm volatile("cp.async.wait_group 1;" ::: "memory")
#define CP_WAIT0() asm volatile("cp.async.wait_group 0;" ::: "memory")

__device__ __forceinline__ void ldmx4(uint32_t& r0, uint32_t& r1, uint32_t& r2, uint32_t& r3, uint32_t addr) {
    asm volatile("ldmatrix.sync.aligned.m8n8.x4.shared.b16 {%0,%1,%2,%3}, [%4];"
        : "=r"(r0), "=r"(r1), "=r"(r2), "=r"(r3) : "r"(addr));
}
__device__ __forceinline__ void mma_bf16(float* c, const uint32_t* a, uint32_t b0, uint32_t b1) {
    asm volatile("mma.sync.aligned.m16n8k16.row.col.f32.bf16.bf16.f32 "
        "{%0,%1,%2,%3}, {%4,%5,%6,%7}, {%8,%9}, {%0,%1,%2,%3};"
        : "+f"(c[0]), "+f"(c[1]), "+f"(c[2]), "+f"(c[3])
        : "r"(a[0]), "r"(a[1]), "r"(a[2]), "r"(a[3]), "r"(b0), "r"(b1));
}

// ==================== split helpers ====================
__device__ __forceinline__ void split4(float4 v, __nv_bfloat16* hp, __nv_bfloat16* lp) {
    __nv_bfloat16 h0=__float2bfloat16_rn(v.x), h1=__float2bfloat16_rn(v.y);
    __nv_bfloat16 h2=__float2bfloat16_rn(v.z), h3=__float2bfloat16_rn(v.w);
    ((__nv_bfloat162*)hp)[0] = __nv_bfloat162{h0,h1};
    ((__nv_bfloat162*)hp)[1] = __nv_bfloat162{h2,h3};
    ((__nv_bfloat162*)lp)[0] = __nv_bfloat162{__float2bfloat16_rn(v.x-__bfloat162float(h0)),
                                              __float2bfloat16_rn(v.y-__bfloat162float(h1))};
    ((__nv_bfloat162*)lp)[1] = __nv_bfloat162{__float2bfloat16_rn(v.z-__bfloat162float(h2)),
                                              __float2bfloat16_rn(v.w-__bfloat162float(h3))};
}
__global__ void split_w_kernel(const float* __restrict__ Wr) {
    int r = blockIdx.x;                 // 0..1023
    int h = r >> 7, p = r & 127;
    int in_row = (p < 64) ? (h*64 + p) : (512 + h*64 + (p - 64));
    int t = threadIdx.x;                // 128 threads
    float4 v = ((const float4*)(Wr + (size_t)in_row * 512))[t];
    split4(v, g_w_hi + (size_t)r*512 + t*4, g_w_lo + (size_t)r*512 + t*4);
}

// ==================== mask compaction ====================
__global__ void zero_cnt_kernel() {
    if (threadIdx.x < Bb) g_cnt[threadIdx.x] = 0;
}
// Block per (j, b); thread = i. Appends (j<<8)|i for unmasked pairs.
__global__ __launch_bounds__(256)
void compact_kernel(const int* __restrict__ adj) {
    int j = blockIdx.x, b = blockIdx.y, i = threadIdx.x;
    int lane = i & 31, w = i >> 5;
    bool keep = adj[((size_t)(b * Ll + i)) * Ll + j] != 1;
    unsigned m = __ballot_sync(0xffffffffu, keep);
    int wpos = __popc(m & ((1u << lane) - 1));
    __shared__ int wcnt[8], wbase[9];
    if (lane == 0) wcnt[w] = __popc(m);
    __syncthreads();
    if (i == 0) {
        int s = 0;
        for (int x = 0; x < 8; x++) { wbase[x] = s; s += wcnt[x]; }
        wbase[8] = atomicAdd(&g_cnt[b], s);
    }
    __syncthreads();
    if (keep) g_list[b * (Ll*Ll) + wbase[8] + wbase[w] + wpos] = (unsigned short)((j << 8) | i);
}

// Gather-split: converts ONLY unmasked rel rows into compacted, list-ordered
// bf16 hi/lo arrays. 2 rows per 256-thread block.
__global__ __launch_bounds__(256)
void split_rel_gather_kernel(const float* __restrict__ rel) {
    int b = blockIdx.y;
    int ent = blockIdx.x * 2 + (threadIdx.x >> 7);
    if (ent >= g_cnt[b]) return;
    int e = g_list[b * (Ll*Ll) + ent];
    int t = threadIdx.x & 127;
    float4 v = ((const float4*)(rel + ((size_t)(b * (Ll*Ll)) + e) * 512))[t];
    size_t o = ((size_t)(b * (Ll*Ll)) + ent) * 512 + t * 4;
    split4(v, g_rel_hi + o, g_rel_lo + o);
}

// ==================== mma.sync relation attention (compacted, M=256) ====================
// CTA = tile t of 256 compacted (j,i) pairs for batch b, 512 threads.
// Per head 24 K-chunks of 64: splits [Ah*Bh | Ah*Bl | Al*Bh]. 3-stage cp.async.
// Warps: 8m x 2n; warp tile 32(M) x 64(N, matched rq/rk halves).
#define NSTG 3
#define STG_BYTES 49152         // A 32KB + B 16KB
#define MMA_SMEM (NSTG*STG_BYTES + 2048 + 512)

__global__ void __launch_bounds__(512, 1) rel_attn_mma_kernel()
{
    extern __shared__ char smem[];
    float* parr = (float*)(smem + NSTG * STG_BYTES);                  // 2*256 floats
    unsigned short* sidx = (unsigned short*)(smem + NSTG * STG_BYTES + 2048);
    const uint32_t sb = smem_u32(smem);
    const int tid = threadIdx.x, lane = tid & 31, w = tid >> 5;
    const int wm = w & 7, wn = w >> 3;
    const int t = blockIdx.x, b = blockIdx.y;

    const int cnt = g_cnt[b];
    if (t * 256 >= cnt) return;
    const size_t rbase = (size_t)(b * (Ll*Ll)) + t * 256;   // compacted row base

    if (tid < 256) {
        int gi = t * 256 + tid;
        sidx[tid] = g_list[b * (Ll*Ll) + (gi < cnt ? gi : cnt - 1)];
    }
    __syncthreads();

    float c[2][8][4];
#pragma unroll
    for (int mt = 0; mt < 2; mt++)
#pragma unroll
        for (int g = 0; g < 8; g++)
#pragma unroll
            for (int e = 0; e < 4; e++) c[mt][g][e] = 0.f;

    auto issue = [&](int gc) {
        const int h = gc / 24, cc = gc % 24;
        const int split = cc >> 3;
        const int kc = (cc & 7) * 64;
        const __nv_bfloat16* Aarr = (split == 2) ? g_rel_lo : g_rel_hi;
        const __nv_bfloat16* Bptr = ((split == 1) ? g_w_lo : g_w_hi) + (size_t)h * 128 * 512;
        const uint32_t stA = sb + (gc % NSTG) * STG_BYTES;
        const uint32_t stB = stA + 32768;
        // A: 256 rows x 64 bf16 = 2048 uint4 (sequential compacted rows)
#pragma unroll
        for (int r4 = 0; r4 < 4; r4++) {
            int idx = tid + r4 * 512;
            int row = idx >> 3, u = idx & 7;
            CP_ASYNC16(stA + SMEM_SWZ(row * 128 + u * 16),
                       Aarr + (rbase + row) * 512 + kc + u * 8);
        }
        // B: 128 rows x 64 bf16 = 1024 uint4
#pragma unroll
        for (int r4 = 0; r4 < 2; r4++) {
            int idx = tid + r4 * 512;
            int row = idx >> 3, u = idx & 7;
            CP_ASYNC16(stB + SMEM_SWZ(row * 128 + u * 16),
                       Bptr + (size_t)row * 512 + kc + u * 8);
        }
        CP_COMMIT();
    };

    issue(0); issue(1);

    for (int gc = 0; gc < 192; gc++) {
        if (gc + 2 < 192) { CP_WAIT1(); } else { CP_WAIT0(); }
        __syncthreads();
        if (gc + 2 < 192) issue(gc + 2);

        const uint32_t stA = sb + (gc % NSTG) * STG_BYTES;
        const uint32_t stB = stA + 32768;
        const int r8 = lane & 7, sel = lane >> 3;
#pragma unroll
        for (int ks = 0; ks < 4; ks++) {
            const int k0 = ks * 16;
            uint32_t a[2][4];
#pragma unroll
            for (int mt = 0; mt < 2; mt++) {
                int row = wm * 32 + mt * 16 + r8 + (sel & 1) * 8;
                int c16 = (k0 >> 3) + (sel >> 1);
                ldmx4(a[mt][0], a[mt][1], a[mt][2], a[mt][3], stA + SMEM_SWZ(row * 128 + c16 * 16));
            }
            uint32_t bq[4][2], bk[4][2];
#pragma unroll
            for (int gp = 0; gp < 2; gp++) {
                int c16 = (k0 >> 3) + (sel & 1);
                {
                    int row = wn * 32 + gp * 16 + r8 + (sel >> 1) * 8;
                    ldmx4(bq[gp*2][0], bq[gp*2][1], bq[gp*2+1][0], bq[gp*2+1][1],
                          stB + SMEM_SWZ(row * 128 + c16 * 16));
                }
                {
                    int row = 64 + wn * 32 + gp * 16 + r8 + (sel >> 1) * 8;
                    ldmx4(bk[gp*2][0], bk[gp*2][1], bk[gp*2+1][0], bk[gp*2+1][1],
                          stB + SMEM_SWZ(row * 128 + c16 * 16));
                }
            }
#pragma unroll
            for (int mt = 0; mt < 2; mt++)
#pragma unroll
                for (int g = 0; g < 4; g++) {
                    mma_bf16(c[mt][g],   a[mt], bq[g][0], bq[g][1]);
                    mma_bf16(c[mt][4+g], a[mt], bk[g][0], bk[g][1]);
                }
        }

        if ((gc % 24) == 23) {
            // -------- epilogue for head h --------
            const int h = gc / 24;
#pragma unroll
            for (int mt = 0; mt < 2; mt++)
#pragma unroll
                for (int rh = 0; rh < 2; rh++) {
                    const int R = wm * 32 + mt * 16 + (lane >> 2) + rh * 8;
                    const int e = sidx[R];
                    const float* qrow = g_q + ((size_t)(b * Ll + (e & 255))) * Ee + h * 64;
                    const float* krow = g_k + ((size_t)(b * Ll + (e >> 8))) * Ee + h * 64;
                    float acc = 0.f;
#pragma unroll
                    for (int g = 0; g < 4; g++) {
                        const int d0 = wn * 32 + g * 8 + 2 * (lane & 3);
                        acc += (qrow[d0]     + c[mt][g][rh*2+0]) * (krow[d0]     + c[mt][4+g][rh*2+0]);
                        acc += (qrow[d0 + 1] + c[mt][g][rh*2+1]) * (krow[d0 + 1] + c[mt][4+g][rh*2+1]);
                    }
                    acc += __shfl_xor_sync(0xffffffffu, acc, 1);
                    acc += __shfl_xor_sync(0xffffffffu, acc, 2);
                    if ((lane & 3) == 0) parr[wn * 256 + R] = acc;
                }
            __syncthreads();
            if (tid < 256 && t * 256 + tid < cnt) {
                const int e = sidx[tid];
                float lg = parr[tid] + parr[256 + tid];
                g_logits[((size_t)(b * Hh + h) * Ll + (e & 255)) * Ll + (e >> 8)] = lg;
            }
            // reset accumulators for next head
#pragma unroll
            for (int mt = 0; mt < 2; mt++)
#pragma unroll
                for (int g = 0; g < 8; g++)
#pragma unroll
                    for (int e2 = 0; e2 < 4; e2++) c[mt][g][e2] = 0.f;
        }
    }
}

// ==================== small GEMMs ====================
__global__ __launch_bounds__(256)
void gemm_qkv_kernel(const float* __restrict__ queries, const float* __restrict__ keys,
                     const float* __restrict__ values,
                     const float* __restrict__ Wq, const float* __restrict__ bq,
                     const float* __restrict__ Wk, const float* __restrict__ bk,
                     const float* __restrict__ Wv, const float* __restrict__ bv)
{
    const int z = blockIdx.z;
    const float* X = (z == 0) ? queries : (z == 1) ? keys : values;
    const float* W = (z == 0) ? Wq : (z == 1) ? Wk : Wv;
    const float* bias = (z == 0) ? bq : (z == 1) ? bk : bv;
    float* Y = (z == 0) ? g_q : (z == 1) ? g_k : g_v;
    const float scale = (z == 0) ? QSCALE : 1.0f;

    __shared__ float Xs[16][64];
    __shared__ float Ws[16][64];
    int tid = threadIdx.x;
    int m0 = blockIdx.y * 64, n0 = blockIdx.x * 64;
    int ty = tid >> 4, tx = tid & 15;
    int r = tid >> 2, c4 = tid & 3;
    float acc[4][4];
#pragma unroll
    for (int a = 0; a < 4; a++)
#pragma unroll
        for (int bb = 0; bb < 4; bb++) acc[a][bb] = 0.f;
    for (int kc = 0; kc < Ee; kc += 16) {
        float4 xv = *(const float4*)(X + (size_t)(m0 + r) * Ee + kc + c4 * 4);
        float4 wv = *(const float4*)(W + (size_t)(n0 + r) * Ee + kc + c4 * 4);
        __syncthreads();
        Xs[c4*4+0][r]=xv.x; Xs[c4*4+1][r]=xv.y; Xs[c4*4+2][r]=xv.z; Xs[c4*4+3][r]=xv.w;
        Ws[c4*4+0][r]=wv.x; Ws[c4*4+1][r]=wv.y; Ws[c4*4+2][r]=wv.z; Ws[c4*4+3][r]=wv.w;
        __syncthreads();
#pragma unroll
        for (int cc = 0; cc < 16; cc++) {
            float4 a = *(const float4*)&Xs[cc][ty*4];
            float4 bv4 = *(const float4*)&Ws[cc][tx*4];
            acc[0][0]+=a.x*bv4.x; acc[0][1]+=a.x*bv4.y; acc[0][2]+=a.x*bv4.z; acc[0][3]+=a.x*bv4.w;
            acc[1][0]+=a.y*bv4.x; acc[1][1]+=a.y*bv4.y; acc[1][2]+=a.y*bv4.z; acc[1][3]+=a.y*bv4.w;
            acc[2][0]+=a.z*bv4.x; acc[2][1]+=a.z*bv4.y; acc[2][2]+=a.z*bv4.z; acc[2][3]+=a.z*bv4.w;
            acc[3][0]+=a.w*bv4.x; acc[3][1]+=a.w*bv4.y; acc[3][2]+=a.w*bv4.z; acc[3][3]+=a.w*bv4.w;
        }
    }
#pragma unroll
    for (int rr = 0; rr < 4; rr++)
#pragma unroll
        for (int cc = 0; cc < 4; cc++)
            Y[(size_t)(m0+ty*4+rr) * Ee + n0+tx*4+cc] = (acc[rr][cc] + bias[n0+tx*4+cc]) * scale;
}

__global__ __launch_bounds__(256)
void gemm_bias_kernel(const float* __restrict__ X, const float* __restrict__ W,
                      const float* __restrict__ bias, float* __restrict__ Y,
                      int Mdim, int Ndim, int Kdim, float scale)
{
    __shared__ float Xs[16][64];
    __shared__ float Ws[16][64];
    int tid = threadIdx.x;
    int m0 = blockIdx.y * 64, n0 = blockIdx.x * 64;
    int ty = tid >> 4, tx = tid & 15;
    int r = tid >> 2, c4 = tid & 3;
    float acc[4][4];
#pragma unroll
    for (int a = 0; a < 4; a++)
#pragma unroll
        for (int bb = 0; bb < 4; bb++) acc[a][bb] = 0.f;
    for (int kc = 0; kc < Kdim; kc += 16) {
        float4 xv = *(const float4*)(X + (size_t)(m0 + r) * Kdim + kc + c4 * 4);
        float4 wv = *(const float4*)(W + (size_t)(n0 + r) * Kdim + kc + c4 * 4);
        __syncthreads();
        Xs[c4*4+0][r]=xv.x; Xs[c4*4+1][r]=xv.y; Xs[c4*4+2][r]=xv.z; Xs[c4*4+3][r]=xv.w;
        Ws[c4*4+0][r]=wv.x; Ws[c4*4+1][r]=wv.y; Ws[c4*4+2][r]=wv.z; Ws[c4*4+3][r]=wv.w;
        __syncthreads();
#pragma unroll
        for (int cc = 0; cc < 16; cc++) {
            float4 a = *(const float4*)&Xs[cc][ty*4];
            float4 bv4 = *(const float4*)&Ws[cc][tx*4];
            acc[0][0]+=a.x*bv4.x; acc[0][1]+=a.x*bv4.y; acc[0][2]+=a.x*bv4.z; acc[0][3]+=a.x*bv4.w;
            acc[1][0]+=a.y*bv4.x; acc[1][1]+=a.y*bv4.y; acc[1][2]+=a.y*bv4.z; acc[1][3]+=a.y*bv4.w;
            acc[2][0]+=a.z*bv4.x; acc[2][1]+=a.z*bv4.y; acc[2][2]+=a.z*bv4.z; acc[2][3]+=a.z*bv4.w;
            acc[3][0]+=a.w*bv4.x; acc[3][1]+=a.w*bv4.y; acc[3][2]+=a.w*bv4.z; acc[3][3]+=a.w*bv4.w;
        }
    }
#pragma unroll
    for (int rr = 0; rr < 4; rr++)
#pragma unroll
        for (int cc = 0; cc < 4; cc++)
            Y[(size_t)(m0+ty*4+rr) * Ndim + n0+tx*4+cc] = (acc[rr][cc] + bias[n0+tx*4+cc]) * scale;
}

// ==================== softmax / PV ====================
__global__ __launch_bounds__(256)
void softmax_kernel(const int* __restrict__ adj, float* __restrict__ out_attn)
{
    int i = blockIdx.x, h = blockIdx.y, b = blockIdx.z;
    int tid = threadIdx.x;
    __shared__ float red1[8];
    __shared__ float red2[8];
    size_t lbase = (((size_t)b * Hh + h) * Ll + i) * Ll;
    float x = g_logits[lbase + tid];
    bool masked = (adj[((size_t)b * Ll + i) * Ll + tid] == 1);
    float xv = masked ? -CUDART_INF_F : x;
    float mx = xv;
#pragma unroll
    for (int o = 16; o > 0; o >>= 1) mx = fmaxf(mx, __shfl_xor_sync(0xffffffffu, mx, o));
    if ((tid & 31) == 0) red1[tid >> 5] = mx;
    __syncthreads();
    mx = red1[0];
#pragma unroll
    for (int ww = 1; ww < 8; ww++) mx = fmaxf(mx, red1[ww]);
    float e = masked ? 0.f : expf(xv - mx);
    float s = e;
#pragma unroll
    for (int o = 16; o > 0; o >>= 1) s += __shfl_xor_sync(0xffffffffu, s, o);
    if ((tid & 31) == 0) red2[tid >> 5] = s;
    __syncthreads();
    s = red2[0];
#pragma unroll
    for (int ww = 1; ww < 8; ww++) s += red2[ww];
    float wgt = e / s;
    g_w[lbase + tid] = wgt;
    out_attn[(((size_t)b * Ll + i) * Ll + tid) * Hh + h] = wgt;
}

#define PV_SMEM_BYTES ((64*256 + 256*64) * 4)
__global__ __launch_bounds__(256, 1)
void pv_kernel()
{
    extern __shared__ float sm[];
    float* Ws = sm;
    float* Vs = sm + 64 * 256;
    int it = blockIdx.x, h = blockIdx.y, b = blockIdx.z;
    int i0 = it * 64;
    int tid = threadIdx.x;
    size_t wbase = (((size_t)b * Hh + h) * Ll + i0) * Ll;
    const float4* wsrc = (const float4*)(g_w + wbase);
    float4* wdst = (float4*)Ws;
    for (int idx = tid; idx < 64 * 256 / 4; idx += 256) wdst[idx] = wsrc[idx];
    float4* vdst = (float4*)Vs;
    for (int idx = tid; idx < 256 * 64 / 4; idx += 256) {
        int jrow = idx >> 4, d4 = idx & 15;
        vdst[idx] = *(const float4*)(g_v + ((size_t)b * Ll + jrow) * Ee + h * 64 + d4 * 4);
    }
    __syncthreads();
    int i = tid >> 2, tq = tid & 3;
    float acc[16];
#pragma unroll
    for (int dd = 0; dd < 16; dd++) acc[dd] = 0.f;
    const float* wrow = Ws + i * 256;
    for (int jj = 0; jj < 256; jj += 4) {
        float4 wv = *(const float4*)(wrow + jj);
#pragma unroll
        for (int u = 0; u < 4; u++) {
            float wsc = (u == 0) ? wv.x : (u == 1) ? wv.y : (u == 2) ? wv.z : wv.w;
            const float* vr = Vs + (jj + u) * 64 + tq * 16;
#pragma unroll
            for (int dd = 0; dd < 16; dd++) acc[dd] += wsc * vr[dd];
        }
    }
    float* op = g_o1 + ((size_t)b * Ll + i0 + i) * Ee + h * 64 + tq * 16;
#pragma unroll
    for (int dd = 0; dd < 16; dd++) op[dd] = acc[dd];
}

// ---------------------------------------------------------------------------
extern "C" void kernel_launch(void* const* d_in, const int* in_sizes, int n_in,
                              void* d_out, int out_size)
{
    (void)in_sizes; (void)n_in; (void)out_size;
    const float* queries  = (const float*)d_in[0];
    const float* keys     = (const float*)d_in[1];
    const float* values   = (const float*)d_in[2];
    const float* relation = (const float*)d_in[3];
    const int*   adj      = (const int*)d_in[4];
    const float* Wq = (const float*)d_in[5];
    const float* bq = (const float*)d_in[6];
    const float* Wk = (const float*)d_in[7];
    const float* bk = (const float*)d_in[8];
    const float* Wv = (const float*)d_in[9];
    const float* bv = (const float*)d_in[10];
    const float* Wr = (const float*)d_in[11];
    const float* Wo = (const float*)d_in[12];
    const float* bo = (const float*)d_in[13];

    float* out      = (float*)d_out;
    float* out_attn = out + Bb * Ll * Ee;

    float *o1p;
    cudaGetSymbolAddress((void**)&o1p, g_o1);

    cudaFuncSetAttribute(rel_attn_mma_kernel, cudaFuncAttributeMaxDynamicSharedMemorySize, MMA_SMEM);
    cudaFuncSetAttribute(pv_kernel, cudaFuncAttributeMaxDynamicSharedMemorySize, PV_SMEM_BYTES);

    zero_cnt_kernel<<<1, 32>>>();
    compact_kernel<<<dim3(Ll, Bb), 256>>>(adj);
    split_rel_gather_kernel<<<dim3(Ll*Ll/2, Bb), 256>>>(relation);
    split_w_kernel<<<1024, 128>>>(Wr);

    gemm_qkv_kernel<<<dim3(Ee/64, (Bb*Ll)/64, 3), 256>>>(queries, keys, values,
                                                         Wq, bq, Wk, bk, Wv, bv);

    rel_attn_mma_kernel<<<dim3(256, Bb), 512, MMA_SMEM>>>();

    softmax_kernel<<<dim3(Ll, Hh, Bb), 256>>>(adj, out_attn);

    pv_kernel<<<dim3(Ll / 64, Hh, Bb), 256, PV_SMEM_BYTES>>>();

    gemm_bias_kernel<<<dim3(Ee/64, (Bb*Ll)/64), 256>>>(o1p, Wo, bo, out, Bb*Ll, Ee, Ee, 1.0f);
}

// round 8
// speedup vs baseline: 1.0528x; 1.0528x over previous
#include <cuda_runtime.h>
#include <cuda_bf16.h>
#include <cstdint>
#include <math_constants.h>

#define Bb 2
#define Ll 256
#define Ee 512
#define Hh 8
#define QSCALE 0.125f

// ---------------- device scratch ----------------
__device__ float g_q[Bb*Ll*Ee];
__device__ float g_k[Bb*Ll*Ee];
__device__ float g_v[Bb*Ll*Ee];
__device__ float g_logits[(size_t)Bb*Hh*Ll*Ll];
__device__ float g_w[(size_t)Bb*Hh*Ll*Ll];
__device__ float g_o1[Bb*Ll*Ee];
// compacted (list-ordered) bf16 hi/lo splits of unmasked relation rows
__device__ __nv_bfloat16 g_rel_hi[(size_t)Bb*Ll*Ll*Ee];
__device__ __nv_bfloat16 g_rel_lo[(size_t)Bb*Ll*Ll*Ee];
__device__ __nv_bfloat16 g_w_hi[1024*512];  // [h*128+p][k]; p<64: Wrq rows, p>=64: Wrk rows
__device__ __nv_bfloat16 g_w_lo[1024*512];
__device__ int g_cnt[Bb];
__device__ unsigned short g_list[Bb*Ll*Ll];   // packed (j<<8)|i of unmasked pairs

// ==================== PTX helpers (sm_103 baseline only) ====================
__device__ __forceinline__ uint32_t smem_u32(const void* p) {
    uint32_t a;
    asm("{ .reg .u64 t; cvta.to.shared.u64 t, %1; cvt.u32.u64 %0, t; }" : "=r"(a) : "l"(p));
    return a;
}
#define SMEM_SWZ(o) ((o) ^ (((o) >> 3) & 0x70))
#define CP_ASYNC16(dst, src) \
    asm volatile("cp.async.cg.shared.global [%0], [%1], 16;" :: "r"(dst), "l"(src))
#define CP_COMMIT() asm volatile("cp.async.commit_group;" ::: "memory")
#define CP_WAIT1() asm volatile("cp.async.wait_group 1;" ::: "memory")
#define CP_WAIT0() asm volatile("cp.async.wait_group 0;" ::: "memory")

__device__ __forceinline__ void ldmx4(uint32_t& r0, uint32_t& r1, uint32_t& r2, uint32_t& r3, uint32_t addr) {
    asm volatile("ldmatrix.sync.aligned.m8n8.x4.shared.b16 {%0,%1,%2,%3}, [%4];"
        : "=r"(r0), "=r"(r1), "=r"(r2), "=r"(r3) : "r"(addr));
}
__device__ __forceinline__ void mma_bf16(float* c, const uint32_t* a, uint32_t b0, uint32_t b1) {
    asm volatile("mma.sync.aligned.m16n8k16.row.col.f32.bf16.bf16.f32 "
        "{%0,%1,%2,%3}, {%4,%5,%6,%7}, {%8,%9}, {%0,%1,%2,%3};"
        : "+f"(c[0]), "+f"(c[1]), "+f"(c[2]), "+f"(c[3])
        : "r"(a[0]), "r"(a[1]), "r"(a[2]), "r"(a[3]), "r"(b0), "r"(b1));
}

// ==================== split helpers ====================
__device__ __forceinline__ void split4(float4 v, __nv_bfloat16* hp, __nv_bfloat16* lp) {
    __nv_bfloat16 h0=__float2bfloat16_rn(v.x), h1=__float2bfloat16_rn(v.y);
    __nv_bfloat16 h2=__float2bfloat16_rn(v.z), h3=__float2bfloat16_rn(v.w);
    ((__nv_bfloat162*)hp)[0] = __nv_bfloat162{h0,h1};
    ((__nv_bfloat162*)hp)[1] = __nv_bfloat162{h2,h3};
    ((__nv_bfloat162*)lp)[0] = __nv_bfloat162{__float2bfloat16_rn(v.x-__bfloat162float(h0)),
                                              __float2bfloat16_rn(v.y-__bfloat162float(h1))};
    ((__nv_bfloat162*)lp)[1] = __nv_bfloat162{__float2bfloat16_rn(v.z-__bfloat162float(h2)),
                                              __float2bfloat16_rn(v.w-__bfloat162float(h3))};
}
__global__ void split_w_kernel(const float* __restrict__ Wr) {
    int r = blockIdx.x;                 // 0..1023
    int h = r >> 7, p = r & 127;
    int in_row = (p < 64) ? (h*64 + p) : (512 + h*64 + (p - 64));
    int t = threadIdx.x;                // 128 threads
    float4 v = ((const float4*)(Wr + (size_t)in_row * 512))[t];
    split4(v, g_w_hi + (size_t)r*512 + t*4, g_w_lo + (size_t)r*512 + t*4);
}

// ==================== mask compaction ====================
__global__ void zero_cnt_kernel() {
    if (threadIdx.x < Bb) g_cnt[threadIdx.x] = 0;
}
// Block per (j, b); thread = i. Appends (j<<8)|i for unmasked pairs.
__global__ __launch_bounds__(256)
void compact_kernel(const int* __restrict__ adj) {
    int j = blockIdx.x, b = blockIdx.y, i = threadIdx.x;
    int lane = i & 31, w = i >> 5;
    bool keep = adj[((size_t)(b * Ll + i)) * Ll + j] != 1;
    unsigned m = __ballot_sync(0xffffffffu, keep);
    int wpos = __popc(m & ((1u << lane) - 1));
    __shared__ int wcnt[8], wbase[9];
    if (lane == 0) wcnt[w] = __popc(m);
    __syncthreads();
    if (i == 0) {
        int s = 0;
        for (int x = 0; x < 8; x++) { wbase[x] = s; s += wcnt[x]; }
        wbase[8] = atomicAdd(&g_cnt[b], s);
    }
    __syncthreads();
    if (keep) g_list[b * (Ll*Ll) + wbase[8] + wbase[w] + wpos] = (unsigned short)((j << 8) | i);
}

// Gather-split: converts ONLY unmasked rel rows into compacted, list-ordered
// bf16 hi/lo arrays. 2 rows per 256-thread block.
__global__ __launch_bounds__(256)
void split_rel_gather_kernel(const float* __restrict__ rel) {
    int b = blockIdx.y;
    int ent = blockIdx.x * 2 + (threadIdx.x >> 7);
    if (ent >= g_cnt[b]) return;
    int e = g_list[b * (Ll*Ll) + ent];
    int t = threadIdx.x & 127;
    float4 v = ((const float4*)(rel + ((size_t)(b * (Ll*Ll)) + e) * 512))[t];
    size_t o = ((size_t)(b * (Ll*Ll)) + ent) * 512 + t * 4;
    split4(v, g_rel_hi + o, g_rel_lo + o);
}

// ==================== mma.sync relation attention (compacted, M=128, occ2) ====
// CTA = tile t of 128 compacted (j,i) pairs for batch b, 256 threads.
// Per head 24 K-chunks of 64: splits [Ah*Bh | Ah*Bl | Al*Bh]. 3-stage cp.async.
// Warps: 4m x 2n; warp tile 32(M) x 64(N, matched rq/rk halves).
#define NSTG 3
#define STG_BYTES 32768         // A 16KB + B 16KB
#define MMA_SMEM (NSTG*STG_BYTES + 1024 + 256)

__global__ void __launch_bounds__(256, 2) rel_attn_mma_kernel()
{
    extern __shared__ char smem[];
    float* parr = (float*)(smem + NSTG * STG_BYTES);
    unsigned short* sidx = (unsigned short*)(smem + NSTG * STG_BYTES + 1024);
    const uint32_t sb = smem_u32(smem);
    const int tid = threadIdx.x, lane = tid & 31, w = tid >> 5;
    const int wm = w & 3, wn = w >> 2;
    const int t = blockIdx.x, b = blockIdx.y;

    const int cnt = g_cnt[b];
    if (t * 128 >= cnt) return;
    const size_t rbase = (size_t)(b * (Ll*Ll)) + t * 128;   // compacted row base

    if (tid < 128) {
        int gi = t * 128 + tid;
        sidx[tid] = g_list[b * (Ll*Ll) + (gi < cnt ? gi : cnt - 1)];
    }
    __syncthreads();

    float c[2][8][4];
#pragma unroll
    for (int mt = 0; mt < 2; mt++)
#pragma unroll
        for (int g = 0; g < 8; g++)
#pragma unroll
            for (int e = 0; e < 4; e++) c[mt][g][e] = 0.f;

    auto issue = [&](int gc) {
        const int h = gc / 24, cc = gc % 24;
        const int split = cc >> 3;
        const int kc = (cc & 7) * 64;
        const __nv_bfloat16* Aarr = (split == 2) ? g_rel_lo : g_rel_hi;
        const __nv_bfloat16* Bptr = ((split == 1) ? g_w_lo : g_w_hi) + (size_t)h * 128 * 512;
        const uint32_t stA = sb + (gc % NSTG) * STG_BYTES;
        const uint32_t stB = stA + 16384;
#pragma unroll
        for (int r4 = 0; r4 < 4; r4++) {
            int idx = tid + r4 * 256;       // 1024 16B units each
            int row = idx >> 3, u = idx & 7;
            CP_ASYNC16(stA + SMEM_SWZ(row * 128 + u * 16),
                       Aarr + (rbase + row) * 512 + kc + u * 8);      // sequential rows
            CP_ASYNC16(stB + SMEM_SWZ(row * 128 + u * 16),
                       Bptr + (size_t)row * 512 + kc + u * 8);
        }
        CP_COMMIT();
    };

    issue(0); issue(1);

    for (int gc = 0; gc < 192; gc++) {
        if (gc + 2 < 192) { CP_WAIT1(); } else { CP_WAIT0(); }
        __syncthreads();
        if (gc + 2 < 192) issue(gc + 2);

        const uint32_t stA = sb + (gc % NSTG) * STG_BYTES;
        const uint32_t stB = stA + 16384;
        const int r8 = lane & 7, sel = lane >> 3;
#pragma unroll
        for (int ks = 0; ks < 4; ks++) {
            const int k0 = ks * 16;
            uint32_t a[2][4];
#pragma unroll
            for (int mt = 0; mt < 2; mt++) {
                int row = wm * 32 + mt * 16 + r8 + (sel & 1) * 8;
                int c16 = (k0 >> 3) + (sel >> 1);
                ldmx4(a[mt][0], a[mt][1], a[mt][2], a[mt][3], stA + SMEM_SWZ(row * 128 + c16 * 16));
            }
            uint32_t bq[4][2], bk[4][2];
#pragma unroll
            for (int gp = 0; gp < 2; gp++) {
                int c16 = (k0 >> 3) + (sel & 1);
                {
                    int row = wn * 32 + gp * 16 + r8 + (sel >> 1) * 8;
                    ldmx4(bq[gp*2][0], bq[gp*2][1], bq[gp*2+1][0], bq[gp*2+1][1],
                          stB + SMEM_SWZ(row * 128 + c16 * 16));
                }
                {
                    int row = 64 + wn * 32 + gp * 16 + r8 + (sel >> 1) * 8;
                    ldmx4(bk[gp*2][0], bk[gp*2][1], bk[gp*2+1][0], bk[gp*2+1][1],
                          stB + SMEM_SWZ(row * 128 + c16 * 16));
                }
            }
#pragma unroll
            for (int mt = 0; mt < 2; mt++)
#pragma unroll
                for (int g = 0; g < 4; g++) {
                    mma_bf16(c[mt][g],   a[mt], bq[g][0], bq[g][1]);
                    mma_bf16(c[mt][4+g], a[mt], bk[g][0], bk[g][1]);
                }
        }

        if ((gc % 24) == 23) {
            // -------- epilogue for head h --------
            const int h = gc / 24;
#pragma unroll
            for (int mt = 0; mt < 2; mt++)
#pragma unroll
                for (int rh = 0; rh < 2; rh++) {
                    const int R = wm * 32 + mt * 16 + (lane >> 2) + rh * 8;
                    const int e = sidx[R];
                    const float* qrow = g_q + ((size_t)(b * Ll + (e & 255))) * Ee + h * 64;
                    const float* krow = g_k + ((size_t)(b * Ll + (e >> 8))) * Ee + h * 64;
                    float acc = 0.f;
#pragma unroll
                    for (int g = 0; g < 4; g++) {
                        const int d0 = wn * 32 + g * 8 + 2 * (lane & 3);
                        acc += (qrow[d0]     + c[mt][g][rh*2+0]) * (krow[d0]     + c[mt][4+g][rh*2+0]);
                        acc += (qrow[d0 + 1] + c[mt][g][rh*2+1]) * (krow[d0 + 1] + c[mt][4+g][rh*2+1]);
                    }
                    acc += __shfl_xor_sync(0xffffffffu, acc, 1);
                    acc += __shfl_xor_sync(0xffffffffu, acc, 2);
                    if ((lane & 3) == 0) parr[wn * 128 + R] = acc;
                }
            __syncthreads();
            if (tid < 128 && t * 128 + tid < cnt) {
                const int e = sidx[tid];
                float lg = parr[tid] + parr[128 + tid];
                g_logits[((size_t)(b * Hh + h) * Ll + (e & 255)) * Ll + (e >> 8)] = lg;
            }
            // reset accumulators for next head
#pragma unroll
            for (int mt = 0; mt < 2; mt++)
#pragma unroll
                for (int g = 0; g < 8; g++)
#pragma unroll
                    for (int e2 = 0; e2 < 4; e2++) c[mt][g][e2] = 0.f;
        }
    }
}

// ==================== small GEMMs ====================
__global__ __launch_bounds__(256)
void gemm_qkv_kernel(const float* __restrict__ queries, const float* __restrict__ keys,
                     const float* __restrict__ values,
                     const float* __restrict__ Wq, const float* __restrict__ bq,
                     const float* __restrict__ Wk, const float* __restrict__ bk,
                     const float* __restrict__ Wv, const float* __restrict__ bv)
{
    const int z = blockIdx.z;
    const float* X = (z == 0) ? queries : (z == 1) ? keys : values;
    const float* W = (z == 0) ? Wq : (z == 1) ? Wk : Wv;
    const float* bias = (z == 0) ? bq : (z == 1) ? bk : bv;
    float* Y = (z == 0) ? g_q : (z == 1) ? g_k : g_v;
    const float scale = (z == 0) ? QSCALE : 1.0f;

    __shared__ float Xs[16][64];
    __shared__ float Ws[16][64];
    int tid = threadIdx.x;
    int m0 = blockIdx.y * 64, n0 = blockIdx.x * 64;
    int ty = tid >> 4, tx = tid & 15;
    int r = tid >> 2, c4 = tid & 3;
    float acc[4][4];
#pragma unroll
    for (int a = 0; a < 4; a++)
#pragma unroll
        for (int bb = 0; bb < 4; bb++) acc[a][bb] = 0.f;
    for (int kc = 0; kc < Ee; kc += 16) {
        float4 xv = *(const float4*)(X + (size_t)(m0 + r) * Ee + kc + c4 * 4);
        float4 wv = *(const float4*)(W + (size_t)(n0 + r) * Ee + kc + c4 * 4);
        __syncthreads();
        Xs[c4*4+0][r]=xv.x; Xs[c4*4+1][r]=xv.y; Xs[c4*4+2][r]=xv.z; Xs[c4*4+3][r]=xv.w;
        Ws[c4*4+0][r]=wv.x; Ws[c4*4+1][r]=wv.y; Ws[c4*4+2][r]=wv.z; Ws[c4*4+3][r]=wv.w;
        __syncthreads();
#pragma unroll
        for (int cc = 0; cc < 16; cc++) {
            float4 a = *(const float4*)&Xs[cc][ty*4];
            float4 bv4 = *(const float4*)&Ws[cc][tx*4];
            acc[0][0]+=a.x*bv4.x; acc[0][1]+=a.x*bv4.y; acc[0][2]+=a.x*bv4.z; acc[0][3]+=a.x*bv4.w;
            acc[1][0]+=a.y*bv4.x; acc[1][1]+=a.y*bv4.y; acc[1][2]+=a.y*bv4.z; acc[1][3]+=a.y*bv4.w;
            acc[2][0]+=a.z*bv4.x; acc[2][1]+=a.z*bv4.y; acc[2][2]+=a.z*bv4.z; acc[2][3]+=a.z*bv4.w;
            acc[3][0]+=a.w*bv4.x; acc[3][1]+=a.w*bv4.y; acc[3][2]+=a.w*bv4.z; acc[3][3]+=a.w*bv4.w;
        }
    }
#pragma unroll
    for (int rr = 0; rr < 4; rr++)
#pragma unroll
        for (int cc = 0; cc < 4; cc++)
            Y[(size_t)(m0+ty*4+rr) * Ee + n0+tx*4+cc] = (acc[rr][cc] + bias[n0+tx*4+cc]) * scale;
}

__global__ __launch_bounds__(256)
void gemm_bias_kernel(const float* __restrict__ X, const float* __restrict__ W,
                      const float* __restrict__ bias, float* __restrict__ Y,
                      int Mdim, int Ndim, int Kdim, float scale)
{
    __shared__ float Xs[16][64];
    __shared__ float Ws[16][64];
    int tid = threadIdx.x;
    int m0 = blockIdx.y * 64, n0 = blockIdx.x * 64;
    int ty = tid >> 4, tx = tid & 15;
    int r = tid >> 2, c4 = tid & 3;
    float acc[4][4];
#pragma unroll
    for (int a = 0; a < 4; a++)
#pragma unroll
        for (int bb = 0; bb < 4; bb++) acc[a][bb] = 0.f;
    for (int kc = 0; kc < Kdim; kc += 16) {
        float4 xv = *(const float4*)(X + (size_t)(m0 + r) * Kdim + kc + c4 * 4);
        float4 wv = *(const float4*)(W + (size_t)(n0 + r) * Kdim + kc + c4 * 4);
        __syncthreads();
        Xs[c4*4+0][r]=xv.x; Xs[c4*4+1][r]=xv.y; Xs[c4*4+2][r]=xv.z; Xs[c4*4+3][r]=xv.w;
        Ws[c4*4+0][r]=wv.x; Ws[c4*4+1][r]=wv.y; Ws[c4*4+2][r]=wv.z; Ws[c4*4+3][r]=wv.w;
        __syncthreads();
#pragma unroll
        for (int cc = 0; cc < 16; cc++) {
            float4 a = *(const float4*)&Xs[cc][ty*4];
            float4 bv4 = *(const float4*)&Ws[cc][tx*4];
            acc[0][0]+=a.x*bv4.x; acc[0][1]+=a.x*bv4.y; acc[0][2]+=a.x*bv4.z; acc[0][3]+=a.x*bv4.w;
            acc[1][0]+=a.y*bv4.x; acc[1][1]+=a.y*bv4.y; acc[1][2]+=a.y*bv4.z; acc[1][3]+=a.y*bv4.w;
            acc[2][0]+=a.z*bv4.x; acc[2][1]+=a.z*bv4.y; acc[2][2]+=a.z*bv4.z; acc[2][3]+=a.z*bv4.w;
            acc[3][0]+=a.w*bv4.x; acc[3][1]+=a.w*bv4.y; acc[3][2]+=a.w*bv4.z; acc[3][3]+=a.w*bv4.w;
        }
    }
#pragma unroll
    for (int rr = 0; rr < 4; rr++)
#pragma unroll
        for (int cc = 0; cc < 4; cc++)
            Y[(size_t)(m0+ty*4+rr) * Ndim + n0+tx*4+cc] = (acc[rr][cc] + bias[n0+tx*4+cc]) * scale;
}

// ==================== softmax / PV ====================
__global__ __launch_bounds__(256)
void softmax_kernel(const int* __restrict__ adj, float* __restrict__ out_attn)
{
    int i = blockIdx.x, h = blockIdx.y, b = blockIdx.z;
    int tid = threadIdx.x;
    __shared__ float red1[8];
    __shared__ float red2[8];
    size_t lbase = (((size_t)b * Hh + h) * Ll + i) * Ll;
    float x = g_logits[lbase + tid];
    bool masked = (adj[((size_t)b * Ll + i) * Ll + tid] == 1);
    float xv = masked ? -CUDART_INF_F : x;
    float mx = xv;
#pragma unroll
    for (int o = 16; o > 0; o >>= 1) mx = fmaxf(mx, __shfl_xor_sync(0xffffffffu, mx, o));
    if ((tid & 31) == 0) red1[tid >> 5] = mx;
    __syncthreads();
    mx = red1[0];
#pragma unroll
    for (int ww = 1; ww < 8; ww++) mx = fmaxf(mx, red1[ww]);
    float e = masked ? 0.f : expf(xv - mx);
    float s = e;
#pragma unroll
    for (int o = 16; o > 0; o >>= 1) s += __shfl_xor_sync(0xffffffffu, s, o);
    if ((tid & 31) == 0) red2[tid >> 5] = s;
    __syncthreads();
    s = red2[0];
#pragma unroll
    for (int ww = 1; ww < 8; ww++) s += red2[ww];
    float wgt = e / s;
    g_w[lbase + tid] = wgt;
    out_attn[(((size_t)b * Ll + i) * Ll + tid) * Hh + h] = wgt;
}

#define PV_SMEM_BYTES ((64*256 + 256*64) * 4)
__global__ __launch_bounds__(256, 1)
void pv_kernel()
{
    extern __shared__ float sm[];
    float* Ws = sm;
    float* Vs = sm + 64 * 256;
    int it = blockIdx.x, h = blockIdx.y, b = blockIdx.z;
    int i0 = it * 64;
    int tid = threadIdx.x;
    size_t wbase = (((size_t)b * Hh + h) * Ll + i0) * Ll;
    const float4* wsrc = (const float4*)(g_w + wbase);
    float4* wdst = (float4*)Ws;
    for (int idx = tid; idx < 64 * 256 / 4; idx += 256) wdst[idx] = wsrc[idx];
    float4* vdst = (float4*)Vs;
    for (int idx = tid; idx < 256 * 64 / 4; idx += 256) {
        int jrow = idx >> 4, d4 = idx & 15;
        vdst[idx] = *(const float4*)(g_v + ((size_t)b * Ll + jrow) * Ee + h * 64 + d4 * 4);
    }
    __syncthreads();
    int i = tid >> 2, tq = tid & 3;
    float acc[16];
#pragma unroll
    for (int dd = 0; dd < 16; dd++) acc[dd] = 0.f;
    const float* wrow = Ws + i * 256;
    for (int jj = 0; jj < 256; jj += 4) {
        float4 wv = *(const float4*)(wrow + jj);
#pragma unroll
        for (int u = 0; u < 4; u++) {
            float wsc = (u == 0) ? wv.x : (u == 1) ? wv.y : (u == 2) ? wv.z : wv.w;
            const float* vr = Vs + (jj + u) * 64 + tq * 16;
#pragma unroll
            for (int dd = 0; dd < 16; dd++) acc[dd] += wsc * vr[dd];
        }
    }
    float* op = g_o1 + ((size_t)b * Ll + i0 + i) * Ee + h * 64 + tq * 16;
#pragma unroll
    for (int dd = 0; dd < 16; dd++) op[dd] = acc[dd];
}

// ---------------------------------------------------------------------------
extern "C" void kernel_launch(void* const* d_in, const int* in_sizes, int n_in,
                              void* d_out, int out_size)
{
    (void)in_sizes; (void)n_in; (void)out_size;
    const float* queries  = (const float*)d_in[0];
    const float* keys     = (const float*)d_in[1];
    const float* values   = (const float*)d_in[2];
    const float* relation = (const float*)d_in[3];
    const int*   adj      = (const int*)d_in[4];
    const float* Wq = (const float*)d_in[5];
    const float* bq = (const float*)d_in[6];
    const float* Wk = (const float*)d_in[7];
    const float* bk = (const float*)d_in[8];
    const float* Wv = (const float*)d_in[9];
    const float* bv = (const float*)d_in[10];
    const float* Wr = (const float*)d_in[11];
    const float* Wo = (const float*)d_in[12];
    const float* bo = (const float*)d_in[13];

    float* out      = (float*)d_out;
    float* out_attn = out + Bb * Ll * Ee;

    float *o1p;
    cudaGetSymbolAddress((void**)&o1p, g_o1);

    cudaFuncSetAttribute(rel_attn_mma_kernel, cudaFuncAttributeMaxDynamicSharedMemorySize, MMA_SMEM);
    cudaFuncSetAttribute(pv_kernel, cudaFuncAttributeMaxDynamicSharedMemorySize, PV_SMEM_BYTES);

    zero_cnt_kernel<<<1, 32>>>();
    compact_kernel<<<dim3(Ll, Bb), 256>>>(adj);
    split_rel_gather_kernel<<<dim3(Ll*Ll/2, Bb), 256>>>(relation);
    split_w_kernel<<<1024, 128>>>(Wr);

    gemm_qkv_kernel<<<dim3(Ee/64, (Bb*Ll)/64, 3), 256>>>(queries, keys, values,
                                                         Wq, bq, Wk, bk, Wv, bv);

    rel_attn_mma_kernel<<<dim3(512, Bb), 256, MMA_SMEM>>>();

    softmax_kernel<<<dim3(Ll, Hh, Bb), 256>>>(adj, out_attn);

    pv_kernel<<<dim3(Ll / 64, Hh, Bb), 256, PV_SMEM_BYTES>>>();

    gemm_bias_kernel<<<dim3(Ee/64, (Bb*Ll)/64), 256>>>(o1p, Wo, bo, out, Bb*Ll, Ee, Ee, 1.0f);
}

// round 9
// speedup vs baseline: 1.1003x; 1.0452x over previous
#include <cuda_runtime.h>
#include <cuda_bf16.h>
#include <cstdint>
#include <math_constants.h>

#define Bb 2
#define Ll 256
#define Ee 512
#define Hh 8
#define QSCALE 0.125f

// ---------------- device scratch ----------------
__device__ float g_q[Bb*Ll*Ee];
__device__ float g_k[Bb*Ll*Ee];
__device__ float g_v[Bb*Ll*Ee];
__device__ float g_logits[(size_t)Bb*Hh*Ll*Ll];
__device__ float g_o1[Bb*Ll*Ee];
// compacted (list-ordered) bf16 hi/lo splits of unmasked relation rows
__device__ __nv_bfloat16 g_rel_hi[(size_t)Bb*Ll*Ll*Ee];
__device__ __nv_bfloat16 g_rel_lo[(size_t)Bb*Ll*Ll*Ee];
__device__ __nv_bfloat16 g_w_hi[1024*512];  // [h*128+p][k]; p<64: Wrq rows, p>=64: Wrk rows
__device__ __nv_bfloat16 g_w_lo[1024*512];
__device__ int g_cnt[Bb];
__device__ unsigned short g_list[Bb*Ll*Ll];   // packed (j<<8)|i of unmasked pairs

// ==================== PTX helpers (sm_103 baseline only) ====================
__device__ __forceinline__ uint32_t smem_u32(const void* p) {
    uint32_t a;
    asm("{ .reg .u64 t; cvta.to.shared.u64 t, %1; cvt.u32.u64 %0, t; }" : "=r"(a) : "l"(p));
    return a;
}
#define SMEM_SWZ(o) ((o) ^ (((o) >> 3) & 0x70))
#define CP_ASYNC16(dst, src) \
    asm volatile("cp.async.cg.shared.global [%0], [%1], 16;" :: "r"(dst), "l"(src))
#define CP_COMMIT() asm volatile("cp.async.commit_group;" ::: "memory")
#define CP_WAIT1() asm volatile("cp.async.wait_group 1;" ::: "memory")
#define CP_WAIT0() asm volatile("cp.async.wait_group 0;" ::: "memory")

__device__ __forceinline__ void ldmx4(uint32_t& r0, uint32_t& r1, uint32_t& r2, uint32_t& r3, uint32_t addr) {
    asm volatile("ldmatrix.sync.aligned.m8n8.x4.shared.b16 {%0,%1,%2,%3}, [%4];"
        : "=r"(r0), "=r"(r1), "=r"(r2), "=r"(r3) : "r"(addr));
}
__device__ __forceinline__ void mma_bf16(float* c, const uint32_t* a, uint32_t b0, uint32_t b1) {
    asm volatile("mma.sync.aligned.m16n8k16.row.col.f32.bf16.bf16.f32 "
        "{%0,%1,%2,%3}, {%4,%5,%6,%7}, {%8,%9}, {%0,%1,%2,%3};"
        : "+f"(c[0]), "+f"(c[1]), "+f"(c[2]), "+f"(c[3])
        : "r"(a[0]), "r"(a[1]), "r"(a[2]), "r"(a[3]), "r"(b0), "r"(b1));
}

// ==================== split helpers ====================
__device__ __forceinline__ void split4(float4 v, __nv_bfloat16* hp, __nv_bfloat16* lp) {
    __nv_bfloat16 h0=__float2bfloat16_rn(v.x), h1=__float2bfloat16_rn(v.y);
    __nv_bfloat16 h2=__float2bfloat16_rn(v.z), h3=__float2bfloat16_rn(v.w);
    ((__nv_bfloat162*)hp)[0] = __nv_bfloat162{h0,h1};
    ((__nv_bfloat162*)hp)[1] = __nv_bfloat162{h2,h3};
    ((__nv_bfloat162*)lp)[0] = __nv_bfloat162{__float2bfloat16_rn(v.x-__bfloat162float(h0)),
                                              __float2bfloat16_rn(v.y-__bfloat162float(h1))};
    ((__nv_bfloat162*)lp)[1] = __nv_bfloat162{__float2bfloat16_rn(v.z-__bfloat162float(h2)),
                                              __float2bfloat16_rn(v.w-__bfloat162float(h3))};
}
// split_w also zeroes g_cnt (block 0) so compact can run next without a
// separate zero kernel (keeps main kernel at launch slot #4 for ncu).
__global__ void split_w_kernel(const float* __restrict__ Wr) {
    if (blockIdx.x == 0 && threadIdx.x < Bb) g_cnt[threadIdx.x] = 0;
    int r = blockIdx.x;                 // 0..1023
    int h = r >> 7, p = r & 127;
    int in_row = (p < 64) ? (h*64 + p) : (512 + h*64 + (p - 64));
    int t = threadIdx.x;                // 128 threads
    float4 v = ((const float4*)(Wr + (size_t)in_row * 512))[t];
    split4(v, g_w_hi + (size_t)r*512 + t*4, g_w_lo + (size_t)r*512 + t*4);
}

// ==================== compact + qkv combo ====================
// blocks 0..511: mask compaction (block=(j,b)). blocks 512..703: q/k/v GEMMs.
__global__ __launch_bounds__(256)
void compact_qkv_kernel(const int* __restrict__ adj,
                        const float* __restrict__ queries, const float* __restrict__ keys,
                        const float* __restrict__ values,
                        const float* __restrict__ Wq, const float* __restrict__ bq,
                        const float* __restrict__ Wk, const float* __restrict__ bk,
                        const float* __restrict__ Wv, const float* __restrict__ bv)
{
    if (blockIdx.x < 512) {
        int j = blockIdx.x & 255, b = blockIdx.x >> 8, i = threadIdx.x;
        int lane = i & 31, w = i >> 5;
        bool keep = adj[((size_t)(b * Ll + i)) * Ll + j] != 1;
        unsigned m = __ballot_sync(0xffffffffu, keep);
        int wpos = __popc(m & ((1u << lane) - 1));
        __shared__ int wcnt[8], wbase[9];
        if (lane == 0) wcnt[w] = __popc(m);
        __syncthreads();
        if (i == 0) {
            int s = 0;
            for (int x = 0; x < 8; x++) { wbase[x] = s; s += wcnt[x]; }
            wbase[8] = atomicAdd(&g_cnt[b], s);
        }
        __syncthreads();
        if (keep) g_list[b * (Ll*Ll) + wbase[8] + wbase[w] + wpos] = (unsigned short)((j << 8) | i);
        return;
    }
    // ---- qkv GEMM part ----
    int bid2 = blockIdx.x - 512;
    int z = bid2 >> 6, rem = bid2 & 63;
    const float* X = (z == 0) ? queries : (z == 1) ? keys : values;
    const float* W = (z == 0) ? Wq : (z == 1) ? Wk : Wv;
    const float* bias = (z == 0) ? bq : (z == 1) ? bk : bv;
    float* Y = (z == 0) ? g_q : (z == 1) ? g_k : g_v;
    const float scale = (z == 0) ? QSCALE : 1.0f;

    __shared__ float Xs[16][64];
    __shared__ float Ws[16][64];
    int tid = threadIdx.x;
    int m0 = (rem >> 3) * 64, n0 = (rem & 7) * 64;
    int ty = tid >> 4, tx = tid & 15;
    int r = tid >> 2, c4 = tid & 3;
    float acc[4][4];
#pragma unroll
    for (int a = 0; a < 4; a++)
#pragma unroll
        for (int bb = 0; bb < 4; bb++) acc[a][bb] = 0.f;
    for (int kc = 0; kc < Ee; kc += 16) {
        float4 xv = *(const float4*)(X + (size_t)(m0 + r) * Ee + kc + c4 * 4);
        float4 wv = *(const float4*)(W + (size_t)(n0 + r) * Ee + kc + c4 * 4);
        __syncthreads();
        Xs[c4*4+0][r]=xv.x; Xs[c4*4+1][r]=xv.y; Xs[c4*4+2][r]=xv.z; Xs[c4*4+3][r]=xv.w;
        Ws[c4*4+0][r]=wv.x; Ws[c4*4+1][r]=wv.y; Ws[c4*4+2][r]=wv.z; Ws[c4*4+3][r]=wv.w;
        __syncthreads();
#pragma unroll
        for (int cc = 0; cc < 16; cc++) {
            float4 a = *(const float4*)&Xs[cc][ty*4];
            float4 bv4 = *(const float4*)&Ws[cc][tx*4];
            acc[0][0]+=a.x*bv4.x; acc[0][1]+=a.x*bv4.y; acc[0][2]+=a.x*bv4.z; acc[0][3]+=a.x*bv4.w;
            acc[1][0]+=a.y*bv4.x; acc[1][1]+=a.y*bv4.y; acc[1][2]+=a.y*bv4.z; acc[1][3]+=a.y*bv4.w;
            acc[2][0]+=a.z*bv4.x; acc[2][1]+=a.z*bv4.y; acc[2][2]+=a.z*bv4.z; acc[2][3]+=a.z*bv4.w;
            acc[3][0]+=a.w*bv4.x; acc[3][1]+=a.w*bv4.y; acc[3][2]+=a.w*bv4.z; acc[3][3]+=a.w*bv4.w;
        }
    }
#pragma unroll
    for (int rr = 0; rr < 4; rr++)
#pragma unroll
        for (int cc = 0; cc < 4; cc++)
            Y[(size_t)(m0+ty*4+rr) * Ee + n0+tx*4+cc] = (acc[rr][cc] + bias[n0+tx*4+cc]) * scale;
}

// Gather-split: converts ONLY unmasked rel rows into compacted, list-ordered
// bf16 hi/lo arrays. 2 rows per 256-thread block.
__global__ __launch_bounds__(256)
void split_rel_gather_kernel(const float* __restrict__ rel) {
    int b = blockIdx.y;
    int ent = blockIdx.x * 2 + (threadIdx.x >> 7);
    if (ent >= g_cnt[b]) return;
    int e = g_list[b * (Ll*Ll) + ent];
    int t = threadIdx.x & 127;
    float4 v = ((const float4*)(rel + ((size_t)(b * (Ll*Ll)) + e) * 512))[t];
    size_t o = ((size_t)(b * (Ll*Ll)) + ent) * 512 + t * 4;
    split4(v, g_rel_hi + o, g_rel_lo + o);
}

// ==================== mma.sync relation attention ====================
// CTA = tile t of 128 compacted pairs, 256 threads, occ 2.
// Step n (192 total): h=n/24, kc=((n/3)&7)*64, sv=n%3 with per-kc order
// (Ah*Bh, Ah*Bl, Al*Bh). A-ring 3x16KB (Ah reused at sv1), B-ring 4x16KB
// (Bh reused at sv2). parr lives in the dead A slot during epilogues.
#define STG 16384
#define SB_B_OFF (3*STG)          // 49152
#define MMA_SMEM (3*STG + 4*STG)  // 114688

__global__ void __launch_bounds__(256, 2) rel_attn_mma_kernel()
{
    extern __shared__ char smem[];
    const uint32_t sb = smem_u32(smem);
    const int tid = threadIdx.x, lane = tid & 31, w = tid >> 5;
    const int wm = w & 3, wn = w >> 2;
    const int t = blockIdx.x, b = blockIdx.y;

    const int cnt = g_cnt[b];
    if (t * 128 >= cnt) return;
    const size_t rbase = (size_t)(b * (Ll*Ll)) + t * 128;   // compacted row base
    const unsigned short* lst = g_list + b * (Ll*Ll);

    float c[2][8][4];
#pragma unroll
    for (int mt = 0; mt < 2; mt++)
#pragma unroll
        for (int g = 0; g < 8; g++)
#pragma unroll
            for (int e = 0; e < 4; e++) c[mt][g][e] = 0.f;

    auto issue = [&](int n) {
        const int sv = n % 3, kcq = n / 3;
        const int kc = (kcq & 7) * 64;
        const int h = n / 24;
        if (sv != 1) {   // load A: sv0 -> Ah, sv2 -> Al
            const __nv_bfloat16* Aarr = (sv == 2) ? g_rel_lo : g_rel_hi;
            const uint32_t stA = sb + ((kcq * 2 + (sv == 2)) % 3) * STG;
#pragma unroll
            for (int r4 = 0; r4 < 4; r4++) {
                int idx = tid + r4 * 256;
                int row = idx >> 3, u = idx & 7;
                CP_ASYNC16(stA + SMEM_SWZ(row * 128 + u * 16),
                           Aarr + (rbase + row) * 512 + kc + u * 8);
            }
        }
        if (sv != 2) {   // load B: sv0 -> Bh, sv1 -> Bl
            const __nv_bfloat16* Bptr = ((sv == 1) ? g_w_lo : g_w_hi) + (size_t)h * 128 * 512;
            const uint32_t stB = sb + SB_B_OFF + ((kcq * 2 + (sv == 1)) & 3) * STG;
#pragma unroll
            for (int r4 = 0; r4 < 4; r4++) {
                int idx = tid + r4 * 256;
                int row = idx >> 3, u = idx & 7;
                CP_ASYNC16(stB + SMEM_SWZ(row * 128 + u * 16),
                           Bptr + (size_t)row * 512 + kc + u * 8);
            }
        }
        CP_COMMIT();
    };

    issue(0); issue(1);

    for (int n = 0; n < 192; n++) {
        if (n + 2 < 192) { CP_WAIT1(); } else { CP_WAIT0(); }
        __syncthreads();
        if (n + 2 < 192) issue(n + 2);

        const int sv = n % 3, kcq = n / 3;
        const uint32_t stA = sb + ((kcq * 2 + (sv == 2)) % 3) * STG;
        const uint32_t stB = sb + SB_B_OFF + ((kcq * 2 + (sv == 1)) & 3) * STG;
        const int r8 = lane & 7, sel = lane >> 3;
#pragma unroll
        for (int ks = 0; ks < 4; ks++) {
            const int k0 = ks * 16;
            uint32_t a[2][4];
#pragma unroll
            for (int mt = 0; mt < 2; mt++) {
                int row = wm * 32 + mt * 16 + r8 + (sel & 1) * 8;
                int c16 = (k0 >> 3) + (sel >> 1);
                ldmx4(a[mt][0], a[mt][1], a[mt][2], a[mt][3], stA + SMEM_SWZ(row * 128 + c16 * 16));
            }
            uint32_t bq[4][2], bk[4][2];
#pragma unroll
            for (int gp = 0; gp < 2; gp++) {
                int c16 = (k0 >> 3) + (sel & 1);
                {
                    int row = wn * 32 + gp * 16 + r8 + (sel >> 1) * 8;
                    ldmx4(bq[gp*2][0], bq[gp*2][1], bq[gp*2+1][0], bq[gp*2+1][1],
                          stB + SMEM_SWZ(row * 128 + c16 * 16));
                }
                {
                    int row = 64 + wn * 32 + gp * 16 + r8 + (sel >> 1) * 8;
                    ldmx4(bk[gp*2][0], bk[gp*2][1], bk[gp*2+1][0], bk[gp*2+1][1],
                          stB + SMEM_SWZ(row * 128 + c16 * 16));
                }
            }
#pragma unroll
            for (int mt = 0; mt < 2; mt++)
#pragma unroll
                for (int g = 0; g < 4; g++) {
                    mma_bf16(c[mt][g],   a[mt], bq[g][0], bq[g][1]);
                    mma_bf16(c[mt][4+g], a[mt], bk[g][0], bk[g][1]);
                }
        }

        if ((n % 24) == 23) {
            // -------- epilogue for head h; parr in the dead A slot --------
            const int h = n / 24;
            float* parr = (float*)(smem + (((n / 3) * 2 + 1) % 3) * STG);
#pragma unroll
            for (int mt = 0; mt < 2; mt++)
#pragma unroll
                for (int rh = 0; rh < 2; rh++) {
                    const int R = wm * 32 + mt * 16 + (lane >> 2) + rh * 8;
                    int gi = t * 128 + R;
                    const int e = lst[gi < cnt ? gi : cnt - 1];
                    const float* qrow = g_q + ((size_t)(b * Ll + (e & 255))) * Ee + h * 64;
                    const float* krow = g_k + ((size_t)(b * Ll + (e >> 8))) * Ee + h * 64;
                    float acc = 0.f;
#pragma unroll
                    for (int g = 0; g < 4; g++) {
                        const int d0 = wn * 32 + g * 8 + 2 * (lane & 3);
                        acc += (qrow[d0]     + c[mt][g][rh*2+0]) * (krow[d0]     + c[mt][4+g][rh*2+0]);
                        acc += (qrow[d0 + 1] + c[mt][g][rh*2+1]) * (krow[d0 + 1] + c[mt][4+g][rh*2+1]);
                    }
                    acc += __shfl_xor_sync(0xffffffffu, acc, 1);
                    acc += __shfl_xor_sync(0xffffffffu, acc, 2);
                    if ((lane & 3) == 0) parr[wn * 128 + R] = acc;
                }
            __syncthreads();
            if (tid < 128 && t * 128 + tid < cnt) {
                const int e = lst[t * 128 + tid];
                float lg = parr[tid] + parr[128 + tid];
                g_logits[((size_t)(b * Hh + h) * Ll + (e & 255)) * Ll + (e >> 8)] = lg;
            }
            __syncthreads();   // parr slot reused as A stage next iteration
#pragma unroll
            for (int mt = 0; mt < 2; mt++)
#pragma unroll
                for (int g = 0; g < 8; g++)
#pragma unroll
                    for (int e2 = 0; e2 < 4; e2++) c[mt][g][e2] = 0.f;
        }
    }
}

// ==================== fused softmax + PV ====================
// Block per (i_tile 64, h, b). Softmax computed in-smem, then PV.
#define SPV_SMEM ((64*256 + 256*64) * 4)
__global__ __launch_bounds__(256, 1)
void softpv_kernel(const int* __restrict__ adj, float* __restrict__ out_attn)
{
    extern __shared__ float sm[];
    float* Ws = sm;            // [64][256] logits -> weights
    float* Vs = sm + 64 * 256; // [256][64]
    int it = blockIdx.x, h = blockIdx.y, b = blockIdx.z;
    int i0 = it * 64;
    int tid = threadIdx.x, lane = tid & 31, w = tid >> 5;

    size_t lb = (((size_t)b * Hh + h) * Ll + i0) * Ll;
    const float4* lsrc = (const float4*)(g_logits + lb);
    float4* wdst = (float4*)Ws;
    for (int idx = tid; idx < 64 * 256 / 4; idx += 256) wdst[idx] = lsrc[idx];
    float4* vdst = (float4*)Vs;
    for (int idx = tid; idx < 256 * 64 / 4; idx += 256) {
        int jrow = idx >> 4, d4 = idx & 15;
        vdst[idx] = *(const float4*)(g_v + ((size_t)b * Ll + jrow) * Ee + h * 64 + d4 * 4);
    }
    __syncthreads();

    // softmax: 8 warps x 8 rows each
    for (int r = w * 8; r < w * 8 + 8; r++) {
        int i = i0 + r;
        const int* arow = adj + ((size_t)(b * Ll + i)) * Ll;
        float v[8]; bool msk[8];
        float mx = -CUDART_INF_F;
#pragma unroll
        for (int u = 0; u < 8; u++) {
            int j = lane + u * 32;
            msk[u] = (arow[j] == 1);
            v[u] = msk[u] ? -CUDART_INF_F : Ws[r * 256 + j];
            mx = fmaxf(mx, v[u]);
        }
#pragma unroll
        for (int o = 16; o > 0; o >>= 1) mx = fmaxf(mx, __shfl_xor_sync(0xffffffffu, mx, o));
        float s = 0.f;
#pragma unroll
        for (int u = 0; u < 8; u++) {
            v[u] = msk[u] ? 0.f : expf(v[u] - mx);
            s += v[u];
        }
#pragma unroll
        for (int o = 16; o > 0; o >>= 1) s += __shfl_xor_sync(0xffffffffu, s, o);
        float inv = 1.0f / s;
#pragma unroll
        for (int u = 0; u < 8; u++) {
            int j = lane + u * 32;
            float wgt = v[u] * inv;
            Ws[r * 256 + j] = wgt;
            out_attn[(((size_t)b * Ll + i) * Ll + j) * Hh + h] = wgt;
        }
    }
    __syncthreads();

    // PV: o1[i, h*64+d] = sum_j Ws[i][j] * Vs[j][d]
    int i = tid >> 2, tq = tid & 3;
    float acc[16];
#pragma unroll
    for (int dd = 0; dd < 16; dd++) acc[dd] = 0.f;
    const float* wrow = Ws + i * 256;
    for (int jj = 0; jj < 256; jj += 4) {
        float4 wv = *(const float4*)(wrow + jj);
#pragma unroll
        for (int u = 0; u < 4; u++) {
            float wsc = (u == 0) ? wv.x : (u == 1) ? wv.y : (u == 2) ? wv.z : wv.w;
            const float* vr = Vs + (jj + u) * 64 + tq * 16;
#pragma unroll
            for (int dd = 0; dd < 16; dd++) acc[dd] += wsc * vr[dd];
        }
    }
    float* op = g_o1 + ((size_t)b * Ll + i0 + i) * Ee + h * 64 + tq * 16;
#pragma unroll
    for (int dd = 0; dd < 16; dd++) op[dd] = acc[dd];
}

// ==================== output GEMM ====================
__global__ __launch_bounds__(256)
void gemm_bias_kernel(const float* __restrict__ X, const float* __restrict__ W,
                      const float* __restrict__ bias, float* __restrict__ Y,
                      int Mdim, int Ndim, int Kdim, float scale)
{
    __shared__ float Xs[16][64];
    __shared__ float Ws[16][64];
    int tid = threadIdx.x;
    int m0 = blockIdx.y * 64, n0 = blockIdx.x * 64;
    int ty = tid >> 4, tx = tid & 15;
    int r = tid >> 2, c4 = tid & 3;
    float acc[4][4];
#pragma unroll
    for (int a = 0; a < 4; a++)
#pragma unroll
        for (int bb = 0; bb < 4; bb++) acc[a][bb] = 0.f;
    for (int kc = 0; kc < Kdim; kc += 16) {
        float4 xv = *(const float4*)(X + (size_t)(m0 + r) * Kdim + kc + c4 * 4);
        float4 wv = *(const float4*)(W + (size_t)(n0 + r) * Kdim + kc + c4 * 4);
        __syncthreads();
        Xs[c4*4+0][r]=xv.x; Xs[c4*4+1][r]=xv.y; Xs[c4*4+2][r]=xv.z; Xs[c4*4+3][r]=xv.w;
        Ws[c4*4+0][r]=wv.x; Ws[c4*4+1][r]=wv.y; Ws[c4*4+2][r]=wv.z; Ws[c4*4+3][r]=wv.w;
        __syncthreads();
#pragma unroll
        for (int cc = 0; cc < 16; cc++) {
            float4 a = *(const float4*)&Xs[cc][ty*4];
            float4 bv4 = *(const float4*)&Ws[cc][tx*4];
            acc[0][0]+=a.x*bv4.x; acc[0][1]+=a.x*bv4.y; acc[0][2]+=a.x*bv4.z; acc[0][3]+=a.x*bv4.w;
            acc[1][0]+=a.y*bv4.x; acc[1][1]+=a.y*bv4.y; acc[1][2]+=a.y*bv4.z; acc[1][3]+=a.y*bv4.w;
            acc[2][0]+=a.z*bv4.x; acc[2][1]+=a.z*bv4.y; acc[2][2]+=a.z*bv4.z; acc[2][3]+=a.z*bv4.w;
            acc[3][0]+=a.w*bv4.x; acc[3][1]+=a.w*bv4.y; acc[3][2]+=a.w*bv4.z; acc[3][3]+=a.w*bv4.w;
        }
    }
#pragma unroll
    for (int rr = 0; rr < 4; rr++)
#pragma unroll
        for (int cc = 0; cc < 4; cc++)
            Y[(size_t)(m0+ty*4+rr) * Ndim + n0+tx*4+cc] = (acc[rr][cc] + bias[n0+tx*4+cc]) * scale;
}

// ---------------------------------------------------------------------------
extern "C" void kernel_launch(void* const* d_in, const int* in_sizes, int n_in,
                              void* d_out, int out_size)
{
    (void)in_sizes; (void)n_in; (void)out_size;
    const float* queries  = (const float*)d_in[0];
    const float* keys     = (const float*)d_in[1];
    const float* values   = (const float*)d_in[2];
    const float* relation = (const float*)d_in[3];
    const int*   adj      = (const int*)d_in[4];
    const float* Wq = (const float*)d_in[5];
    const float* bq = (const float*)d_in[6];
    const float* Wk = (const float*)d_in[7];
    const float* bk = (const float*)d_in[8];
    const float* Wv = (const float*)d_in[9];
    const float* bv = (const float*)d_in[10];
    const float* Wr = (const float*)d_in[11];
    const float* Wo = (const float*)d_in[12];
    const float* bo = (const float*)d_in[13];

    float* out      = (float*)d_out;
    float* out_attn = out + Bb * Ll * Ee;

    float *o1p;
    cudaGetSymbolAddress((void**)&o1p, g_o1);

    cudaFuncSetAttribute(rel_attn_mma_kernel, cudaFuncAttributeMaxDynamicSharedMemorySize, MMA_SMEM);
    cudaFuncSetAttribute(softpv_kernel, cudaFuncAttributeMaxDynamicSharedMemorySize, SPV_SMEM);

    // 1: split Wr (+ zero g_cnt)
    split_w_kernel<<<1024, 128>>>(Wr);
    // 2: compaction + q/k/v projections
    compact_qkv_kernel<<<704, 256>>>(adj, queries, keys, values,
                                     Wq, bq, Wk, bk, Wv, bv);
    // 3: gather-split unmasked relation rows
    split_rel_gather_kernel<<<dim3(Ll*Ll/2, Bb), 256>>>(relation);
    // 4: main MMA kernel (profiled slot)
    rel_attn_mma_kernel<<<dim3(512, Bb), 256, MMA_SMEM>>>();
    // 5: fused softmax + PV
    softpv_kernel<<<dim3(Ll / 64, Hh, Bb), 256, SPV_SMEM>>>(adj, out_attn);
    // 6: output projection
    gemm_bias_kernel<<<dim3(Ee/64, (Bb*Ll)/64), 256>>>(o1p, Wo, bo, out, Bb*Ll, Ee, Ee, 1.0f);
}

// round 10
// speedup vs baseline: 1.1182x; 1.0162x over previous
#include <cuda_runtime.h>
#include <cuda_bf16.h>
#include <cstdint>
#include <math_constants.h>

#define Bb 2
#define Ll 256
#define Ee 512
#define Hh 8
#define QSCALE 0.125f

// ---------------- device scratch ----------------
__device__ float g_q[Bb*Ll*Ee];
__device__ float g_k[Bb*Ll*Ee];
__device__ float g_v[Bb*Ll*Ee];
__device__ float g_logits[(size_t)Bb*Hh*Ll*Ll];
__device__ float g_o1[Bb*Ll*Ee];
__device__ __nv_bfloat16 g_rel_hi[(size_t)Bb*Ll*Ll*Ee];
__device__ __nv_bfloat16 g_rel_lo[(size_t)Bb*Ll*Ll*Ee];
__device__ __nv_bfloat16 g_w_hi[1024*512];  // [h*128+p][k]; p<64: Wrq rows, p>=64: Wrk rows
__device__ __nv_bfloat16 g_w_lo[1024*512];
__device__ int g_cnt[Bb];
__device__ unsigned short g_list[Bb*Ll*Ll];

// ==================== PTX helpers ====================
__device__ __forceinline__ uint32_t smem_u32(const void* p) {
    uint32_t a;
    asm("{ .reg .u64 t; cvta.to.shared.u64 t, %1; cvt.u32.u64 %0, t; }" : "=r"(a) : "l"(p));
    return a;
}
#define SMEM_SWZ(o) ((o) ^ (((o) >> 3) & 0x70))
#define CP_ASYNC16(dst, src) \
    asm volatile("cp.async.cg.shared.global [%0], [%1], 16;" :: "r"(dst), "l"(src))
#define CP_COMMIT() asm volatile("cp.async.commit_group;" ::: "memory")
#define CP_WAIT1() asm volatile("cp.async.wait_group 1;" ::: "memory")
#define CP_WAIT0() asm volatile("cp.async.wait_group 0;" ::: "memory")

__device__ __forceinline__ void ldmx4(uint32_t& r0, uint32_t& r1, uint32_t& r2, uint32_t& r3, uint32_t addr) {
    asm volatile("ldmatrix.sync.aligned.m8n8.x4.shared.b16 {%0,%1,%2,%3}, [%4];"
        : "=r"(r0), "=r"(r1), "=r"(r2), "=r"(r3) : "r"(addr));
}
__device__ __forceinline__ void mma_bf16(float* c, const uint32_t* a, uint32_t b0, uint32_t b1) {
    asm volatile("mma.sync.aligned.m16n8k16.row.col.f32.bf16.bf16.f32 "
        "{%0,%1,%2,%3}, {%4,%5,%6,%7}, {%8,%9}, {%0,%1,%2,%3};"
        : "+f"(c[0]), "+f"(c[1]), "+f"(c[2]), "+f"(c[3])
        : "r"(a[0]), "r"(a[1]), "r"(a[2]), "r"(a[3]), "r"(b0), "r"(b1));
}

// ==================== split helpers ====================
__device__ __forceinline__ void split4(float4 v, __nv_bfloat16* hp, __nv_bfloat16* lp) {
    __nv_bfloat16 h0=__float2bfloat16_rn(v.x), h1=__float2bfloat16_rn(v.y);
    __nv_bfloat16 h2=__float2bfloat16_rn(v.z), h3=__float2bfloat16_rn(v.w);
    ((__nv_bfloat162*)hp)[0] = __nv_bfloat162{h0,h1};
    ((__nv_bfloat162*)hp)[1] = __nv_bfloat162{h2,h3};
    ((__nv_bfloat162*)lp)[0] = __nv_bfloat162{__float2bfloat16_rn(v.x-__bfloat162float(h0)),
                                              __float2bfloat16_rn(v.y-__bfloat162float(h1))};
    ((__nv_bfloat162*)lp)[1] = __nv_bfloat162{__float2bfloat16_rn(v.z-__bfloat162float(h2)),
                                              __float2bfloat16_rn(v.w-__bfloat162float(h3))};
}
__global__ void split_w_kernel(const float* __restrict__ Wr) {
    if (blockIdx.x == 0 && threadIdx.x < Bb) g_cnt[threadIdx.x] = 0;
    int r = blockIdx.x;
    int h = r >> 7, p = r & 127;
    int in_row = (p < 64) ? (h*64 + p) : (512 + h*64 + (p - 64));
    int t = threadIdx.x;
    float4 v = ((const float4*)(Wr + (size_t)in_row * 512))[t];
    split4(v, g_w_hi + (size_t)r*512 + t*4, g_w_lo + (size_t)r*512 + t*4);
}

// ==================== compact + qkv combo ====================
__global__ __launch_bounds__(256)
void compact_qkv_kernel(const int* __restrict__ adj,
                        const float* __restrict__ queries, const float* __restrict__ keys,
                        const float* __restrict__ values,
                        const float* __restrict__ Wq, const float* __restrict__ bq,
                        const float* __restrict__ Wk, const float* __restrict__ bk,
                        const float* __restrict__ Wv, const float* __restrict__ bv)
{
    if (blockIdx.x < 512) {
        int j = blockIdx.x & 255, b = blockIdx.x >> 8, i = threadIdx.x;
        int lane = i & 31, w = i >> 5;
        bool keep = adj[((size_t)(b * Ll + i)) * Ll + j] != 1;
        unsigned m = __ballot_sync(0xffffffffu, keep);
        int wpos = __popc(m & ((1u << lane) - 1));
        __shared__ int wcnt[8], wbase[9];
        if (lane == 0) wcnt[w] = __popc(m);
        __syncthreads();
        if (i == 0) {
            int s = 0;
            for (int x = 0; x < 8; x++) { wbase[x] = s; s += wcnt[x]; }
            wbase[8] = atomicAdd(&g_cnt[b], s);
        }
        __syncthreads();
        if (keep) g_list[b * (Ll*Ll) + wbase[8] + wbase[w] + wpos] = (unsigned short)((j << 8) | i);
        return;
    }
    int bid2 = blockIdx.x - 512;
    int z = bid2 >> 6, rem = bid2 & 63;
    const float* X = (z == 0) ? queries : (z == 1) ? keys : values;
    const float* W = (z == 0) ? Wq : (z == 1) ? Wk : Wv;
    const float* bias = (z == 0) ? bq : (z == 1) ? bk : bv;
    float* Y = (z == 0) ? g_q : (z == 1) ? g_k : g_v;
    const float scale = (z == 0) ? QSCALE : 1.0f;

    __shared__ float Xs[16][64];
    __shared__ float Ws[16][64];
    int tid = threadIdx.x;
    int m0 = (rem >> 3) * 64, n0 = (rem & 7) * 64;
    int ty = tid >> 4, tx = tid & 15;
    int r = tid >> 2, c4 = tid & 3;
    float acc[4][4];
#pragma unroll
    for (int a = 0; a < 4; a++)
#pragma unroll
        for (int bb = 0; bb < 4; bb++) acc[a][bb] = 0.f;
    for (int kc = 0; kc < Ee; kc += 16) {
        float4 xv = *(const float4*)(X + (size_t)(m0 + r) * Ee + kc + c4 * 4);
        float4 wv = *(const float4*)(W + (size_t)(n0 + r) * Ee + kc + c4 * 4);
        __syncthreads();
        Xs[c4*4+0][r]=xv.x; Xs[c4*4+1][r]=xv.y; Xs[c4*4+2][r]=xv.z; Xs[c4*4+3][r]=xv.w;
        Ws[c4*4+0][r]=wv.x; Ws[c4*4+1][r]=wv.y; Ws[c4*4+2][r]=wv.z; Ws[c4*4+3][r]=wv.w;
        __syncthreads();
#pragma unroll
        for (int cc = 0; cc < 16; cc++) {
            float4 a = *(const float4*)&Xs[cc][ty*4];
            float4 bv4 = *(const float4*)&Ws[cc][tx*4];
            acc[0][0]+=a.x*bv4.x; acc[0][1]+=a.x*bv4.y; acc[0][2]+=a.x*bv4.z; acc[0][3]+=a.x*bv4.w;
            acc[1][0]+=a.y*bv4.x; acc[1][1]+=a.y*bv4.y; acc[1][2]+=a.y*bv4.z; acc[1][3]+=a.y*bv4.w;
            acc[2][0]+=a.z*bv4.x; acc[2][1]+=a.z*bv4.y; acc[2][2]+=a.z*bv4.z; acc[2][3]+=a.z*bv4.w;
            acc[3][0]+=a.w*bv4.x; acc[3][1]+=a.w*bv4.y; acc[3][2]+=a.w*bv4.z; acc[3][3]+=a.w*bv4.w;
        }
    }
#pragma unroll
    for (int rr = 0; rr < 4; rr++)
#pragma unroll
        for (int cc = 0; cc < 4; cc++)
            Y[(size_t)(m0+ty*4+rr) * Ee + n0+tx*4+cc] = (acc[rr][cc] + bias[n0+tx*4+cc]) * scale;
}

// Gather-split: converts ONLY unmasked rel rows (compacted, list-ordered).
__global__ __launch_bounds__(256)
void split_rel_gather_kernel(const float* __restrict__ rel) {
    int b = blockIdx.y;
    int ent = blockIdx.x * 2 + (threadIdx.x >> 7);
    if (ent >= g_cnt[b]) return;
    int e = g_list[b * (Ll*Ll) + ent];
    int t = threadIdx.x & 127;
    float4 v = ((const float4*)(rel + ((size_t)(b * (Ll*Ll)) + e) * 512))[t];
    size_t o = ((size_t)(b * (Ll*Ll)) + ent) * 512 + t * 4;
    split4(v, g_rel_hi + o, g_rel_lo + o);
}

// ==================== mma.sync relation attention (kc-merged) ====================
// CTA = tile of 128 compacted pairs, 256 threads, occ 1.
// 64 kc-iterations; per kc all 4 tiles (Ah,Al,Bh,Bl; 64KB) resident.
// Inner ks: load Ah/Al/Bh/Bl fragments ONCE (12 LDSM), fire 48 MMAs
// (AhBh + AhBl + AlBh). 3-deep 64KB ring, prefetch distance 2.
#define KSTG 65536
#define MMA_SMEM (3*KSTG)        // 196608

__global__ void __launch_bounds__(256, 1) rel_attn_mma_kernel()
{
    extern __shared__ char smem[];
    const uint32_t sb = smem_u32(smem);
    const int tid = threadIdx.x, lane = tid & 31, w = tid >> 5;
    const int wm = w & 3, wn = w >> 2;
    const int t = blockIdx.x, b = blockIdx.y;

    const int cnt = g_cnt[b];
    if (t * 128 >= cnt) return;
    const size_t rbase = (size_t)(b * (Ll*Ll)) + t * 128;
    const unsigned short* lst = g_list + b * (Ll*Ll);

    float c[2][8][4];
#pragma unroll
    for (int mt = 0; mt < 2; mt++)
#pragma unroll
        for (int g = 0; g < 8; g++)
#pragma unroll
            for (int e = 0; e < 4; e++) c[mt][g][e] = 0.f;

    auto issue = [&](int kc) {
        const int h = kc >> 3;
        const int kcol = (kc & 7) * 64;
        const uint32_t st = sb + (kc % 3) * KSTG;
        const __nv_bfloat16* Bh = g_w_hi + (size_t)h * 128 * 512;
        const __nv_bfloat16* Bl = g_w_lo + (size_t)h * 128 * 512;
#pragma unroll
        for (int r4 = 0; r4 < 4; r4++) {
            int idx = tid + r4 * 256;
            int row = idx >> 3, u = idx & 7;
            uint32_t so = SMEM_SWZ(row * 128 + u * 16);
            size_t go = (size_t)row * 512 + kcol + u * 8;
            CP_ASYNC16(st + so,         g_rel_hi + (rbase + row) * 512 + kcol + u * 8);
            CP_ASYNC16(st + 16384 + so, g_rel_lo + (rbase + row) * 512 + kcol + u * 8);
            CP_ASYNC16(st + 32768 + so, Bh + go);
            CP_ASYNC16(st + 49152 + so, Bl + go);
        }
        CP_COMMIT();
    };

    issue(0); issue(1);

    for (int kc = 0; kc < 64; kc++) {
        if (kc + 2 < 64) { CP_WAIT1(); } else { CP_WAIT0(); }
        __syncthreads();
        if (kc + 2 < 64) issue(kc + 2);

        const uint32_t st = sb + (kc % 3) * KSTG;
        const int r8 = lane & 7, sel = lane >> 3;
#pragma unroll
        for (int ks = 0; ks < 4; ks++) {
            uint32_t ah[2][4], al[2][4];
#pragma unroll
            for (int mt = 0; mt < 2; mt++) {
                int row = wm * 32 + mt * 16 + r8 + (sel & 1) * 8;
                int c16 = ks * 2 + (sel >> 1);
                uint32_t so = SMEM_SWZ(row * 128 + c16 * 16);
                ldmx4(ah[mt][0], ah[mt][1], ah[mt][2], ah[mt][3], st + so);
                ldmx4(al[mt][0], al[mt][1], al[mt][2], al[mt][3], st + 16384 + so);
            }
            uint32_t bhq[4][2], bhk[4][2], blq[4][2], blk[4][2];
#pragma unroll
            for (int gp = 0; gp < 2; gp++) {
                int c16 = ks * 2 + (sel & 1);
                int rowq = wn * 32 + gp * 16 + r8 + (sel >> 1) * 8;
                uint32_t soq = SMEM_SWZ(rowq * 128 + c16 * 16);
                ldmx4(bhq[gp*2][0], bhq[gp*2][1], bhq[gp*2+1][0], bhq[gp*2+1][1], st + 32768 + soq);
                ldmx4(blq[gp*2][0], blq[gp*2][1], blq[gp*2+1][0], blq[gp*2+1][1], st + 49152 + soq);
                int rowk = 64 + rowq;
                uint32_t sok = SMEM_SWZ(rowk * 128 + c16 * 16);
                ldmx4(bhk[gp*2][0], bhk[gp*2][1], bhk[gp*2+1][0], bhk[gp*2+1][1], st + 32768 + sok);
                ldmx4(blk[gp*2][0], blk[gp*2][1], blk[gp*2+1][0], blk[gp*2+1][1], st + 49152 + sok);
            }
#pragma unroll
            for (int mt = 0; mt < 2; mt++)
#pragma unroll
                for (int g = 0; g < 4; g++) {
                    mma_bf16(c[mt][g],   ah[mt], bhq[g][0], bhq[g][1]);   // Ah*Bh
                    mma_bf16(c[mt][4+g], ah[mt], bhk[g][0], bhk[g][1]);
                    mma_bf16(c[mt][g],   ah[mt], blq[g][0], blq[g][1]);   // Ah*Bl
                    mma_bf16(c[mt][4+g], ah[mt], blk[g][0], blk[g][1]);
                    mma_bf16(c[mt][g],   al[mt], bhq[g][0], bhq[g][1]);   // Al*Bh
                    mma_bf16(c[mt][4+g], al[mt], bhk[g][0], bhk[g][1]);
                }
        }

        if ((kc & 7) == 7) {
            // -------- epilogue for head h; parr in the just-consumed stage --------
            const int h = kc >> 3;
            float* parr = (float*)(smem + (kc % 3) * KSTG);
#pragma unroll
            for (int mt = 0; mt < 2; mt++)
#pragma unroll
                for (int rh = 0; rh < 2; rh++) {
                    const int R = wm * 32 + mt * 16 + (lane >> 2) + rh * 8;
                    int gi = t * 128 + R;
                    const int e = lst[gi < cnt ? gi : cnt - 1];
                    const float* qrow = g_q + ((size_t)(b * Ll + (e & 255))) * Ee + h * 64;
                    const float* krow = g_k + ((size_t)(b * Ll + (e >> 8))) * Ee + h * 64;
                    float acc = 0.f;
#pragma unroll
                    for (int g = 0; g < 4; g++) {
                        const int d0 = wn * 32 + g * 8 + 2 * (lane & 3);
                        acc += (qrow[d0]     + c[mt][g][rh*2+0]) * (krow[d0]     + c[mt][4+g][rh*2+0]);
                        acc += (qrow[d0 + 1] + c[mt][g][rh*2+1]) * (krow[d0 + 1] + c[mt][4+g][rh*2+1]);
                    }
                    acc += __shfl_xor_sync(0xffffffffu, acc, 1);
                    acc += __shfl_xor_sync(0xffffffffu, acc, 2);
                    if ((lane & 3) == 0) parr[wn * 128 + R] = acc;
                }
            __syncthreads();
            if (tid < 128 && t * 128 + tid < cnt) {
                const int e = lst[t * 128 + tid];
                float lg = parr[tid] + parr[128 + tid];
                g_logits[((size_t)(b * Hh + h) * Ll + (e & 255)) * Ll + (e >> 8)] = lg;
            }
            __syncthreads();   // stage reused by cp.async next iteration
#pragma unroll
            for (int mt = 0; mt < 2; mt++)
#pragma unroll
                for (int g = 0; g < 8; g++)
#pragma unroll
                    for (int e2 = 0; e2 < 4; e2++) c[mt][g][e2] = 0.f;
        }
    }
}

// ==================== fused softmax + PV ====================
#define SPV_SMEM ((64*256 + 256*64) * 4)
__global__ __launch_bounds__(256, 1)
void softpv_kernel(const int* __restrict__ adj, float* __restrict__ out_attn)
{
    extern __shared__ float sm[];
    float* Ws = sm;
    float* Vs = sm + 64 * 256;
    int it = blockIdx.x, h = blockIdx.y, b = blockIdx.z;
    int i0 = it * 64;
    int tid = threadIdx.x, lane = tid & 31, w = tid >> 5;

    size_t lb = (((size_t)b * Hh + h) * Ll + i0) * Ll;
    const float4* lsrc = (const float4*)(g_logits + lb);
    float4* wdst = (float4*)Ws;
    for (int idx = tid; idx < 64 * 256 / 4; idx += 256) wdst[idx] = lsrc[idx];
    float4* vdst = (float4*)Vs;
    for (int idx = tid; idx < 256 * 64 / 4; idx += 256) {
        int jrow = idx >> 4, d4 = idx & 15;
        vdst[idx] = *(const float4*)(g_v + ((size_t)b * Ll + jrow) * Ee + h * 64 + d4 * 4);
    }
    __syncthreads();

    for (int r = w * 8; r < w * 8 + 8; r++) {
        int i = i0 + r;
        const int* arow = adj + ((size_t)(b * Ll + i)) * Ll;
        float v[8]; bool msk[8];
        float mx = -CUDART_INF_F;
#pragma unroll
        for (int u = 0; u < 8; u++) {
            int j = lane + u * 32;
            msk[u] = (arow[j] == 1);
            v[u] = msk[u] ? -CUDART_INF_F : Ws[r * 256 + j];
            mx = fmaxf(mx, v[u]);
        }
#pragma unroll
        for (int o = 16; o > 0; o >>= 1) mx = fmaxf(mx, __shfl_xor_sync(0xffffffffu, mx, o));
        float s = 0.f;
#pragma unroll
        for (int u = 0; u < 8; u++) {
            v[u] = msk[u] ? 0.f : expf(v[u] - mx);
            s += v[u];
        }
#pragma unroll
        for (int o = 16; o > 0; o >>= 1) s += __shfl_xor_sync(0xffffffffu, s, o);
        float inv = 1.0f / s;
#pragma unroll
        for (int u = 0; u < 8; u++) {
            int j = lane + u * 32;
            float wgt = v[u] * inv;
            Ws[r * 256 + j] = wgt;
            out_attn[(((size_t)b * Ll + i) * Ll + j) * Hh + h] = wgt;
        }
    }
    __syncthreads();

    int i = tid >> 2, tq = tid & 3;
    float acc[16];
#pragma unroll
    for (int dd = 0; dd < 16; dd++) acc[dd] = 0.f;
    const float* wrow = Ws + i * 256;
    for (int jj = 0; jj < 256; jj += 4) {
        float4 wv = *(const float4*)(wrow + jj);
#pragma unroll
        for (int u = 0; u < 4; u++) {
            float wsc = (u == 0) ? wv.x : (u == 1) ? wv.y : (u == 2) ? wv.z : wv.w;
            const float* vr = Vs + (jj + u) * 64 + tq * 16;
#pragma unroll
            for (int dd = 0; dd < 16; dd++) acc[dd] += wsc * vr[dd];
        }
    }
    float* op = g_o1 + ((size_t)b * Ll + i0 + i) * Ee + h * 64 + tq * 16;
#pragma unroll
    for (int dd = 0; dd < 16; dd++) op[dd] = acc[dd];
}

// ==================== output GEMM ====================
__global__ __launch_bounds__(256)
void gemm_bias_kernel(const float* __restrict__ X, const float* __restrict__ W,
                      const float* __restrict__ bias, float* __restrict__ Y,
                      int Mdim, int Ndim, int Kdim, float scale)
{
    __shared__ float Xs[16][64];
    __shared__ float Ws[16][64];
    int tid = threadIdx.x;
    int m0 = blockIdx.y * 64, n0 = blockIdx.x * 64;
    int ty = tid >> 4, tx = tid & 15;
    int r = tid >> 2, c4 = tid & 3;
    float acc[4][4];
#pragma unroll
    for (int a = 0; a < 4; a++)
#pragma unroll
        for (int bb = 0; bb < 4; bb++) acc[a][bb] = 0.f;
    for (int kc = 0; kc < Kdim; kc += 16) {
        float4 xv = *(const float4*)(X + (size_t)(m0 + r) * Kdim + kc + c4 * 4);
        float4 wv = *(const float4*)(W + (size_t)(n0 + r) * Kdim + kc + c4 * 4);
        __syncthreads();
        Xs[c4*4+0][r]=xv.x; Xs[c4*4+1][r]=xv.y; Xs[c4*4+2][r]=xv.z; Xs[c4*4+3][r]=xv.w;
        Ws[c4*4+0][r]=wv.x; Ws[c4*4+1][r]=wv.y; Ws[c4*4+2][r]=wv.z; Ws[c4*4+3][r]=wv.w;
        __syncthreads();
#pragma unroll
        for (int cc = 0; cc < 16; cc++) {
            float4 a = *(const float4*)&Xs[cc][ty*4];
            float4 bv4 = *(const float4*)&Ws[cc][tx*4];
            acc[0][0]+=a.x*bv4.x; acc[0][1]+=a.x*bv4.y; acc[0][2]+=a.x*bv4.z; acc[0][3]+=a.x*bv4.w;
            acc[1][0]+=a.y*bv4.x; acc[1][1]+=a.y*bv4.y; acc[1][2]+=a.y*bv4.z; acc[1][3]+=a.y*bv4.w;
            acc[2][0]+=a.z*bv4.x; acc[2][1]+=a.z*bv4.y; acc[2][2]+=a.z*bv4.z; acc[2][3]+=a.z*bv4.w;
            acc[3][0]+=a.w*bv4.x; acc[3][1]+=a.w*bv4.y; acc[3][2]+=a.w*bv4.z; acc[3][3]+=a.w*bv4.w;
        }
    }
#pragma unroll
    for (int rr = 0; rr < 4; rr++)
#pragma unroll
        for (int cc = 0; cc < 4; cc++)
            Y[(size_t)(m0+ty*4+rr) * Ndim + n0+tx*4+cc] = (acc[rr][cc] + bias[n0+tx*4+cc]) * scale;
}

// ---------------------------------------------------------------------------
extern "C" void kernel_launch(void* const* d_in, const int* in_sizes, int n_in,
                              void* d_out, int out_size)
{
    (void)in_sizes; (void)n_in; (void)out_size;
    const float* queries  = (const float*)d_in[0];
    const float* keys     = (const float*)d_in[1];
    const float* values   = (const float*)d_in[2];
    const float* relation = (const float*)d_in[3];
    const int*   adj      = (const int*)d_in[4];
    const float* Wq = (const float*)d_in[5];
    const float* bq = (const float*)d_in[6];
    const float* Wk = (const float*)d_in[7];
    const float* bk = (const float*)d_in[8];
    const float* Wv = (const float*)d_in[9];
    const float* bv = (const float*)d_in[10];
    const float* Wr = (const float*)d_in[11];
    const float* Wo = (const float*)d_in[12];
    const float* bo = (const float*)d_in[13];

    float* out      = (float*)d_out;
    float* out_attn = out + Bb * Ll * Ee;

    float *o1p;
    cudaGetSymbolAddress((void**)&o1p, g_o1);

    cudaFuncSetAttribute(rel_attn_mma_kernel, cudaFuncAttributeMaxDynamicSharedMemorySize, MMA_SMEM);
    cudaFuncSetAttribute(softpv_kernel, cudaFuncAttributeMaxDynamicSharedMemorySize, SPV_SMEM);

    split_w_kernel<<<1024, 128>>>(Wr);
    compact_qkv_kernel<<<704, 256>>>(adj, queries, keys, values,
                                     Wq, bq, Wk, bk, Wv, bv);
    split_rel_gather_kernel<<<dim3(Ll*Ll/2, Bb), 256>>>(relation);
    rel_attn_mma_kernel<<<dim3(512, Bb), 256, MMA_SMEM>>>();
    softpv_kernel<<<dim3(Ll / 64, Hh, Bb), 256, SPV_SMEM>>>(adj, out_attn);
    gemm_bias_kernel<<<dim3(Ee/64, (Bb*Ll)/64), 256>>>(o1p, Wo, bo, out, Bb*Ll, Ee, Ee, 1.0f);
}

// round 11
// speedup vs baseline: 1.4276x; 1.2767x over previous
#include <cuda_runtime.h>
#include <cuda_bf16.h>
#include <cstdint>
#include <math_constants.h>

#define Bb 2
#define Ll 256
#define Ee 512
#define Hh 8
#define QSCALE 0.125f

// ---------------- device scratch ----------------
__device__ float g_q[Bb*Ll*Ee];
__device__ float g_k[Bb*Ll*Ee];
__device__ float g_v[Bb*Ll*Ee];
__device__ float g_logits[(size_t)Bb*Hh*Ll*Ll];
__device__ float g_o1[Bb*Ll*Ee];
// tf32-rounded (rne) fp32 copies; relation rows compacted in list order
__device__ float g_rel_t32[(size_t)Bb*Ll*Ll*Ee];
__device__ float g_w_t32[1024*512];   // [h*128+p][k]; p<64: Wrq rows, p>=64: Wrk rows
__device__ int g_cnt[Bb];
__device__ unsigned short g_list[Bb*Ll*Ll];

// ==================== PTX helpers ====================
__device__ __forceinline__ uint32_t smem_u32(const void* p) {
    uint32_t a;
    asm("{ .reg .u64 t; cvta.to.shared.u64 t, %1; cvt.u32.u64 %0, t; }" : "=r"(a) : "l"(p));
    return a;
}
#define SMEM_SWZ(o) ((o) ^ (((o) >> 3) & 0x70))
#define CP_ASYNC16(dst, src) \
    asm volatile("cp.async.cg.shared.global [%0], [%1], 16;" :: "r"(dst), "l"(src))
#define CP_COMMIT() asm volatile("cp.async.commit_group;" ::: "memory")
#define CP_WAIT1() asm volatile("cp.async.wait_group 1;" ::: "memory")
#define CP_WAIT0() asm volatile("cp.async.wait_group 0;" ::: "memory")

__device__ __forceinline__ void ldmx4(uint32_t& r0, uint32_t& r1, uint32_t& r2, uint32_t& r3, uint32_t addr) {
    asm volatile("ldmatrix.sync.aligned.m8n8.x4.shared.b16 {%0,%1,%2,%3}, [%4];"
        : "=r"(r0), "=r"(r1), "=r"(r2), "=r"(r3) : "r"(addr));
}
// m16n8k8 tf32 MMA (fp32 accumulate)
__device__ __forceinline__ void mma_tf32(float* c, const uint32_t* a, uint32_t b0, uint32_t b1) {
    asm volatile("mma.sync.aligned.m16n8k8.row.col.f32.tf32.tf32.f32 "
        "{%0,%1,%2,%3}, {%4,%5,%6,%7}, {%8,%9}, {%0,%1,%2,%3};"
        : "+f"(c[0]), "+f"(c[1]), "+f"(c[2]), "+f"(c[3])
        : "r"(a[0]), "r"(a[1]), "r"(a[2]), "r"(a[3]), "r"(b0), "r"(b1));
}
__device__ __forceinline__ float to_tf32(float x) {
    uint32_t o; asm("cvt.rna.tf32.f32 %0, %1;" : "=r"(o) : "f"(x));
    return __uint_as_float(o);
}

// ==================== split kernels (tf32 rne rounding) ====================
__global__ void split_w_kernel(const float* __restrict__ Wr) {
    if (blockIdx.x == 0 && threadIdx.x < Bb) g_cnt[threadIdx.x] = 0;
    int r = blockIdx.x;
    int h = r >> 7, p = r & 127;
    int in_row = (p < 64) ? (h*64 + p) : (512 + h*64 + (p - 64));
    int t = threadIdx.x;
    float4 v = ((const float4*)(Wr + (size_t)in_row * 512))[t];
    float4 o; o.x = to_tf32(v.x); o.y = to_tf32(v.y); o.z = to_tf32(v.z); o.w = to_tf32(v.w);
    ((float4*)(g_w_t32 + (size_t)r * 512))[t] = o;
}

// ==================== compact + qkv combo ====================
__global__ __launch_bounds__(256)
void compact_qkv_kernel(const int* __restrict__ adj,
                        const float* __restrict__ queries, const float* __restrict__ keys,
                        const float* __restrict__ values,
                        const float* __restrict__ Wq, const float* __restrict__ bq,
                        const float* __restrict__ Wk, const float* __restrict__ bk,
                        const float* __restrict__ Wv, const float* __restrict__ bv)
{
    if (blockIdx.x < 512) {
        int j = blockIdx.x & 255, b = blockIdx.x >> 8, i = threadIdx.x;
        int lane = i & 31, w = i >> 5;
        bool keep = adj[((size_t)(b * Ll + i)) * Ll + j] != 1;
        unsigned m = __ballot_sync(0xffffffffu, keep);
        int wpos = __popc(m & ((1u << lane) - 1));
        __shared__ int wcnt[8], wbase[9];
        if (lane == 0) wcnt[w] = __popc(m);
        __syncthreads();
        if (i == 0) {
            int s = 0;
            for (int x = 0; x < 8; x++) { wbase[x] = s; s += wcnt[x]; }
            wbase[8] = atomicAdd(&g_cnt[b], s);
        }
        __syncthreads();
        if (keep) g_list[b * (Ll*Ll) + wbase[8] + wbase[w] + wpos] = (unsigned short)((j << 8) | i);
        return;
    }
    int bid2 = blockIdx.x - 512;
    int z = bid2 >> 6, rem = bid2 & 63;
    const float* X = (z == 0) ? queries : (z == 1) ? keys : values;
    const float* W = (z == 0) ? Wq : (z == 1) ? Wk : Wv;
    const float* bias = (z == 0) ? bq : (z == 1) ? bk : bv;
    float* Y = (z == 0) ? g_q : (z == 1) ? g_k : g_v;
    const float scale = (z == 0) ? QSCALE : 1.0f;

    __shared__ float Xs[16][64];
    __shared__ float Ws[16][64];
    int tid = threadIdx.x;
    int m0 = (rem >> 3) * 64, n0 = (rem & 7) * 64;
    int ty = tid >> 4, tx = tid & 15;
    int r = tid >> 2, c4 = tid & 3;
    float acc[4][4];
#pragma unroll
    for (int a = 0; a < 4; a++)
#pragma unroll
        for (int bb = 0; bb < 4; bb++) acc[a][bb] = 0.f;
    for (int kc = 0; kc < Ee; kc += 16) {
        float4 xv = *(const float4*)(X + (size_t)(m0 + r) * Ee + kc + c4 * 4);
        float4 wv = *(const float4*)(W + (size_t)(n0 + r) * Ee + kc + c4 * 4);
        __syncthreads();
        Xs[c4*4+0][r]=xv.x; Xs[c4*4+1][r]=xv.y; Xs[c4*4+2][r]=xv.z; Xs[c4*4+3][r]=xv.w;
        Ws[c4*4+0][r]=wv.x; Ws[c4*4+1][r]=wv.y; Ws[c4*4+2][r]=wv.z; Ws[c4*4+3][r]=wv.w;
        __syncthreads();
#pragma unroll
        for (int cc = 0; cc < 16; cc++) {
            float4 a = *(const float4*)&Xs[cc][ty*4];
            float4 bv4 = *(const float4*)&Ws[cc][tx*4];
            acc[0][0]+=a.x*bv4.x; acc[0][1]+=a.x*bv4.y; acc[0][2]+=a.x*bv4.z; acc[0][3]+=a.x*bv4.w;
            acc[1][0]+=a.y*bv4.x; acc[1][1]+=a.y*bv4.y; acc[1][2]+=a.y*bv4.z; acc[1][3]+=a.y*bv4.w;
            acc[2][0]+=a.z*bv4.x; acc[2][1]+=a.z*bv4.y; acc[2][2]+=a.z*bv4.z; acc[2][3]+=a.z*bv4.w;
            acc[3][0]+=a.w*bv4.x; acc[3][1]+=a.w*bv4.y; acc[3][2]+=a.w*bv4.z; acc[3][3]+=a.w*bv4.w;
        }
    }
#pragma unroll
    for (int rr = 0; rr < 4; rr++)
#pragma unroll
        for (int cc = 0; cc < 4; cc++)
            Y[(size_t)(m0+ty*4+rr) * Ee + n0+tx*4+cc] = (acc[rr][cc] + bias[n0+tx*4+cc]) * scale;
}

// Gather + tf32-round ONLY unmasked rel rows (compacted, list-ordered).
__global__ __launch_bounds__(256)
void split_rel_gather_kernel(const float* __restrict__ rel) {
    int b = blockIdx.y;
    int ent = blockIdx.x * 2 + (threadIdx.x >> 7);
    if (ent >= g_cnt[b]) return;
    int e = g_list[b * (Ll*Ll) + ent];
    int t = threadIdx.x & 127;
    float4 v = ((const float4*)(rel + ((size_t)(b * (Ll*Ll)) + e) * 512))[t];
    float4 o; o.x = to_tf32(v.x); o.y = to_tf32(v.y); o.z = to_tf32(v.z); o.w = to_tf32(v.w);
    ((float4*)(g_rel_t32 + ((size_t)(b * (Ll*Ll)) + ent) * 512))[t] = o;
}

// ==================== tf32 mma.sync relation attention ====================
// CTA = tile of 128 compacted pairs, 256 threads, occ 2.
// Single tf32 product (rne-prerounded). 128 kc-chunks of 32 fp32 (per head 16).
// Stage = A 16KB + B 16KB = 32KB; 3-deep ring (96KB), prefetch distance 2.
// Warps 4m x 2n; warp tile 32(M) x 64(N = matched rq/rk halves).
// Per ks (k=8): 2 A ldmatrix + 4 B ldmatrix -> 16 MMA (m16n8k8).
#define KSTG 32768
#define MMA_SMEM (3*KSTG)        // 98304

__global__ void __launch_bounds__(256, 2) rel_attn_mma_kernel()
{
    extern __shared__ char smem[];
    const uint32_t sb = smem_u32(smem);
    const int tid = threadIdx.x, lane = tid & 31, w = tid >> 5;
    const int wm = w & 3, wn = w >> 2;
    const int t = blockIdx.x, b = blockIdx.y;

    const int cnt = g_cnt[b];
    if (t * 128 >= cnt) return;
    const size_t rbase = (size_t)(b * (Ll*Ll)) + t * 128;
    const unsigned short* lst = g_list + b * (Ll*Ll);

    float c[2][8][4];
#pragma unroll
    for (int mt = 0; mt < 2; mt++)
#pragma unroll
        for (int g = 0; g < 8; g++)
#pragma unroll
            for (int e = 0; e < 4; e++) c[mt][g][e] = 0.f;

    auto issue = [&](int kc) {
        const int h = kc >> 4;
        const int kcol = (kc & 15) * 32;
        const uint32_t st = sb + (kc % 3) * KSTG;
        const float* Bp = g_w_t32 + (size_t)h * 128 * 512;
#pragma unroll
        for (int r4 = 0; r4 < 4; r4++) {
            int idx = tid + r4 * 256;       // 1024 16B units each of A and B
            int row = idx >> 3, u = idx & 7;
            uint32_t so = SMEM_SWZ(row * 128 + u * 16);
            CP_ASYNC16(st + so,         g_rel_t32 + (rbase + row) * 512 + kcol + u * 4);
            CP_ASYNC16(st + 16384 + so, Bp + (size_t)row * 512 + kcol + u * 4);
        }
        CP_COMMIT();
    };

    issue(0); issue(1);

    for (int kc = 0; kc < 128; kc++) {
        if (kc + 2 < 128) { CP_WAIT1(); } else { CP_WAIT0(); }
        __syncthreads();
        if (kc + 2 < 128) issue(kc + 2);

        const uint32_t stA = sb + (kc % 3) * KSTG;
        const uint32_t stB = stA + 16384;
        const int r8 = lane & 7, sel = lane >> 3;
#pragma unroll
        for (int ks = 0; ks < 4; ks++) {
            // A fragments (tf32 via ldmatrix-b16 quadrant mapping)
            uint32_t a[2][4];
#pragma unroll
            for (int mt = 0; mt < 2; mt++) {
                int row = wm * 32 + mt * 16 + r8 + (sel & 1) * 8;
                int unit = ks * 2 + (sel >> 1);
                ldmx4(a[mt][0], a[mt][1], a[mt][2], a[mt][3],
                      stA + SMEM_SWZ(row * 128 + unit * 16));
            }
            // B fragments: one ldmx4 covers two n8-groups (b0,b1 each)
            uint32_t bq[4][2], bk[4][2];
#pragma unroll
            for (int pr = 0; pr < 2; pr++) {
                int rowq = wn * 32 + pr * 16 + r8 + (sel >> 1) * 8;
                int unit = ks * 2 + (sel & 1);
                ldmx4(bq[pr*2][0], bq[pr*2][1], bq[pr*2+1][0], bq[pr*2+1][1],
                      stB + SMEM_SWZ(rowq * 128 + unit * 16));
                int rowk = 64 + rowq;
                ldmx4(bk[pr*2][0], bk[pr*2][1], bk[pr*2+1][0], bk[pr*2+1][1],
                      stB + SMEM_SWZ(rowk * 128 + unit * 16));
            }
#pragma unroll
            for (int mt = 0; mt < 2; mt++)
#pragma unroll
                for (int g = 0; g < 4; g++) {
                    mma_tf32(c[mt][g],   a[mt], bq[g][0], bq[g][1]);
                    mma_tf32(c[mt][4+g], a[mt], bk[g][0], bk[g][1]);
                }
        }

        if ((kc & 15) == 15) {
            // -------- epilogue for head h; parr in the just-consumed stage --------
            const int h = kc >> 4;
            float* parr = (float*)(smem + (kc % 3) * KSTG);
#pragma unroll
            for (int mt = 0; mt < 2; mt++)
#pragma unroll
                for (int rh = 0; rh < 2; rh++) {
                    const int R = wm * 32 + mt * 16 + (lane >> 2) + rh * 8;
                    int gi = t * 128 + R;
                    const int e = lst[gi < cnt ? gi : cnt - 1];
                    const float* qrow = g_q + ((size_t)(b * Ll + (e & 255))) * Ee + h * 64;
                    const float* krow = g_k + ((size_t)(b * Ll + (e >> 8))) * Ee + h * 64;
                    float acc = 0.f;
#pragma unroll
                    for (int g = 0; g < 4; g++) {
                        const int d0 = wn * 32 + g * 8 + 2 * (lane & 3);
                        acc += (qrow[d0]     + c[mt][g][rh*2+0]) * (krow[d0]     + c[mt][4+g][rh*2+0]);
                        acc += (qrow[d0 + 1] + c[mt][g][rh*2+1]) * (krow[d0 + 1] + c[mt][4+g][rh*2+1]);
                    }
                    acc += __shfl_xor_sync(0xffffffffu, acc, 1);
                    acc += __shfl_xor_sync(0xffffffffu, acc, 2);
                    if ((lane & 3) == 0) parr[wn * 128 + R] = acc;
                }
            __syncthreads();
            if (tid < 128 && t * 128 + tid < cnt) {
                const int e = lst[t * 128 + tid];
                float lg = parr[tid] + parr[128 + tid];
                g_logits[((size_t)(b * Hh + h) * Ll + (e & 255)) * Ll + (e >> 8)] = lg;
            }
            __syncthreads();   // stage reused by cp.async next iteration
#pragma unroll
            for (int mt = 0; mt < 2; mt++)
#pragma unroll
                for (int g = 0; g < 8; g++)
#pragma unroll
                    for (int e2 = 0; e2 < 4; e2++) c[mt][g][e2] = 0.f;
        }
    }
}

// ==================== fused softmax + PV ====================
#define SPV_SMEM ((64*256 + 256*64) * 4)
__global__ __launch_bounds__(256, 1)
void softpv_kernel(const int* __restrict__ adj, float* __restrict__ out_attn)
{
    extern __shared__ float sm[];
    float* Ws = sm;
    float* Vs = sm + 64 * 256;
    int it = blockIdx.x, h = blockIdx.y, b = blockIdx.z;
    int i0 = it * 64;
    int tid = threadIdx.x, lane = tid & 31, w = tid >> 5;

    size_t lb = (((size_t)b * Hh + h) * Ll + i0) * Ll;
    const float4* lsrc = (const float4*)(g_logits + lb);
    float4* wdst = (float4*)Ws;
    for (int idx = tid; idx < 64 * 256 / 4; idx += 256) wdst[idx] = lsrc[idx];
    float4* vdst = (float4*)Vs;
    for (int idx = tid; idx < 256 * 64 / 4; idx += 256) {
        int jrow = idx >> 4, d4 = idx & 15;
        vdst[idx] = *(const float4*)(g_v + ((size_t)b * Ll + jrow) * Ee + h * 64 + d4 * 4);
    }
    __syncthreads();

    for (int r = w * 8; r < w * 8 + 8; r++) {
        int i = i0 + r;
        const int* arow = adj + ((size_t)(b * Ll + i)) * Ll;
        float v[8]; bool msk[8];
        float mx = -CUDART_INF_F;
#pragma unroll
        for (int u = 0; u < 8; u++) {
            int j = lane + u * 32;
            msk[u] = (arow[j] == 1);
            v[u] = msk[u] ? -CUDART_INF_F : Ws[r * 256 + j];
            mx = fmaxf(mx, v[u]);
        }
#pragma unroll
        for (int o = 16; o > 0; o >>= 1) mx = fmaxf(mx, __shfl_xor_sync(0xffffffffu, mx, o));
        float s = 0.f;
#pragma unroll
        for (int u = 0; u < 8; u++) {
            v[u] = msk[u] ? 0.f : expf(v[u] - mx);
            s += v[u];
        }
#pragma unroll
        for (int o = 16; o > 0; o >>= 1) s += __shfl_xor_sync(0xffffffffu, s, o);
        float inv = 1.0f / s;
#pragma unroll
        for (int u = 0; u < 8; u++) {
            int j = lane + u * 32;
            float wgt = v[u] * inv;
            Ws[r * 256 + j] = wgt;
            out_attn[(((size_t)b * Ll + i) * Ll + j) * Hh + h] = wgt;
        }
    }
    __syncthreads();

    int i = tid >> 2, tq = tid & 3;
    float acc[16];
#pragma unroll
    for (int dd = 0; dd < 16; dd++) acc[dd] = 0.f;
    const float* wrow = Ws + i * 256;
    for (int jj = 0; jj < 256; jj += 4) {
        float4 wv = *(const float4*)(wrow + jj);
#pragma unroll
        for (int u = 0; u < 4; u++) {
            float wsc = (u == 0) ? wv.x : (u == 1) ? wv.y : (u == 2) ? wv.z : wv.w;
            const float* vr = Vs + (jj + u) * 64 + tq * 16;
#pragma unroll
            for (int dd = 0; dd < 16; dd++) acc[dd] += wsc * vr[dd];
        }
    }
    float* op = g_o1 + ((size_t)b * Ll + i0 + i) * Ee + h * 64 + tq * 16;
#pragma unroll
    for (int dd = 0; dd < 16; dd++) op[dd] = acc[dd];
}

// ==================== output GEMM ====================
__global__ __launch_bounds__(256)
void gemm_bias_kernel(const float* __restrict__ X, const float* __restrict__ W,
                      const float* __restrict__ bias, float* __restrict__ Y,
                      int Mdim, int Ndim, int Kdim, float scale)
{
    __shared__ float Xs[16][64];
    __shared__ float Ws[16][64];
    int tid = threadIdx.x;
    int m0 = blockIdx.y * 64, n0 = blockIdx.x * 64;
    int ty = tid >> 4, tx = tid & 15;
    int r = tid >> 2, c4 = tid & 3;
    float acc[4][4];
#pragma unroll
    for (int a = 0; a < 4; a++)
#pragma unroll
        for (int bb = 0; bb < 4; bb++) acc[a][bb] = 0.f;
    for (int kc = 0; kc < Kdim; kc += 16) {
        float4 xv = *(const float4*)(X + (size_t)(m0 + r) * Kdim + kc + c4 * 4);
        float4 wv = *(const float4*)(W + (size_t)(n0 + r) * Kdim + kc + c4 * 4);
        __syncthreads();
        Xs[c4*4+0][r]=xv.x; Xs[c4*4+1][r]=xv.y; Xs[c4*4+2][r]=xv.z; Xs[c4*4+3][r]=xv.w;
        Ws[c4*4+0][r]=wv.x; Ws[c4*4+1][r]=wv.y; Ws[c4*4+2][r]=wv.z; Ws[c4*4+3][r]=wv.w;
        __syncthreads();
#pragma unroll
        for (int cc = 0; cc < 16; cc++) {
            float4 a = *(const float4*)&Xs[cc][ty*4];
            float4 bv4 = *(const float4*)&Ws[cc][tx*4];
            acc[0][0]+=a.x*bv4.x; acc[0][1]+=a.x*bv4.y; acc[0][2]+=a.x*bv4.z; acc[0][3]+=a.x*bv4.w;
            acc[1][0]+=a.y*bv4.x; acc[1][1]+=a.y*bv4.y; acc[1][2]+=a.y*bv4.z; acc[1][3]+=a.y*bv4.w;
            acc[2][0]+=a.z*bv4.x; acc[2][1]+=a.z*bv4.y; acc[2][2]+=a.z*bv4.z; acc[2][3]+=a.z*bv4.w;
            acc[3][0]+=a.w*bv4.x; acc[3][1]+=a.w*bv4.y; acc[3][2]+=a.w*bv4.z; acc[3][3]+=a.w*bv4.w;
        }
    }
#pragma unroll
    for (int rr = 0; rr < 4; rr++)
#pragma unroll
        for (int cc = 0; cc < 4; cc++)
            Y[(size_t)(m0+ty*4+rr) * Ndim + n0+tx*4+cc] = (acc[rr][cc] + bias[n0+tx*4+cc]) * scale;
}

// ---------------------------------------------------------------------------
extern "C" void kernel_launch(void* const* d_in, const int* in_sizes, int n_in,
                              void* d_out, int out_size)
{
    (void)in_sizes; (void)n_in; (void)out_size;
    const float* queries  = (const float*)d_in[0];
    const float* keys     = (const float*)d_in[1];
    const float* values   = (const float*)d_in[2];
    const float* relation = (const float*)d_in[3];
    const int*   adj      = (const int*)d_in[4];
    const float* Wq = (const float*)d_in[5];
    const float* bq = (const float*)d_in[6];
    const float* Wk = (const float*)d_in[7];
    const float* bk = (const float*)d_in[8];
    const float* Wv = (const float*)d_in[9];
    const float* bv = (const float*)d_in[10];
    const float* Wr = (const float*)d_in[11];
    const float* Wo = (const float*)d_in[12];
    const float* bo = (const float*)d_in[13];

    float* out      = (float*)d_out;
    float* out_attn = out + Bb * Ll * Ee;

    float *o1p;
    cudaGetSymbolAddress((void**)&o1p, g_o1);

    cudaFuncSetAttribute(rel_attn_mma_kernel, cudaFuncAttributeMaxDynamicSharedMemorySize, MMA_SMEM);
    cudaFuncSetAttribute(softpv_kernel, cudaFuncAttributeMaxDynamicSharedMemorySize, SPV_SMEM);

    split_w_kernel<<<1024, 128>>>(Wr);
    compact_qkv_kernel<<<704, 256>>>(adj, queries, keys, values,
                                     Wq, bq, Wk, bk, Wv, bv);
    split_rel_gather_kernel<<<dim3(Ll*Ll/2, Bb), 256>>>(relation);
    rel_attn_mma_kernel<<<dim3(512, Bb), 256, MMA_SMEM>>>();
    softpv_kernel<<<dim3(Ll / 64, Hh, Bb), 256, SPV_SMEM>>>(adj, out_attn);
    gemm_bias_kernel<<<dim3(Ee/64, (Bb*Ll)/64), 256>>>(o1p, Wo, bo, out, Bb*Ll, Ee, Ee, 1.0f);
}

// round 12
// speedup vs baseline: 1.4381x; 1.0074x over previous
#include <cuda_runtime.h>
#include <cuda_bf16.h>
#include <cstdint>
#include <math_constants.h>

#define Bb 2
#define Ll 256
#define Ee 512
#define Hh 8
#define QSCALE 0.125f

// ---------------- device scratch ----------------
__device__ float g_q[Bb*Ll*Ee];
__device__ float g_k[Bb*Ll*Ee];
__device__ float g_v[Bb*Ll*Ee];
__device__ float g_logits[(size_t)Bb*Hh*Ll*Ll];
__device__ float g_o1[Bb*Ll*Ee];
// tf32-rounded (rne) fp32 copies; relation rows compacted in list order
__device__ float g_rel_t32[(size_t)Bb*Ll*Ll*Ee];
__device__ float g_w_t32[1024*512];   // [h*128+p][k]; p<64: Wrq rows, p>=64: Wrk rows
__device__ int g_cnt[Bb];
__device__ unsigned short g_list[Bb*Ll*Ll];

// ==================== PTX helpers ====================
__device__ __forceinline__ uint32_t smem_u32(const void* p) {
    uint32_t a;
    asm("{ .reg .u64 t; cvta.to.shared.u64 t, %1; cvt.u32.u64 %0, t; }" : "=r"(a) : "l"(p));
    return a;
}
#define SMEM_SWZ(o) ((o) ^ (((o) >> 3) & 0x70))
#define CP_ASYNC16(dst, src) \
    asm volatile("cp.async.cg.shared.global [%0], [%1], 16;" :: "r"(dst), "l"(src))
#define CP_COMMIT() asm volatile("cp.async.commit_group;" ::: "memory")
#define CP_WAIT1() asm volatile("cp.async.wait_group 1;" ::: "memory")
#define CP_WAIT0() asm volatile("cp.async.wait_group 0;" ::: "memory")

__device__ __forceinline__ void ldmx4(uint32_t& r0, uint32_t& r1, uint32_t& r2, uint32_t& r3, uint32_t addr) {
    asm volatile("ldmatrix.sync.aligned.m8n8.x4.shared.b16 {%0,%1,%2,%3}, [%4];"
        : "=r"(r0), "=r"(r1), "=r"(r2), "=r"(r3) : "r"(addr));
}
// m16n8k8 tf32 MMA (fp32 accumulate)
__device__ __forceinline__ void mma_tf32(float* c, const uint32_t* a, uint32_t b0, uint32_t b1) {
    asm volatile("mma.sync.aligned.m16n8k8.row.col.f32.tf32.tf32.f32 "
        "{%0,%1,%2,%3}, {%4,%5,%6,%7}, {%8,%9}, {%0,%1,%2,%3};"
        : "+f"(c[0]), "+f"(c[1]), "+f"(c[2]), "+f"(c[3])
        : "r"(a[0]), "r"(a[1]), "r"(a[2]), "r"(a[3]), "r"(b0), "r"(b1));
}
__device__ __forceinline__ float to_tf32(float x) {
    uint32_t o; asm("cvt.rna.tf32.f32 %0, %1;" : "=r"(o) : "f"(x));
    return __uint_as_float(o);
}

// ==================== split kernels (tf32 rne rounding) ====================
__global__ void split_w_kernel(const float* __restrict__ Wr) {
    if (blockIdx.x == 0 && threadIdx.x < Bb) g_cnt[threadIdx.x] = 0;
    int r = blockIdx.x;
    int h = r >> 7, p = r & 127;
    int in_row = (p < 64) ? (h*64 + p) : (512 + h*64 + (p - 64));
    int t = threadIdx.x;
    float4 v = ((const float4*)(Wr + (size_t)in_row * 512))[t];
    float4 o; o.x = to_tf32(v.x); o.y = to_tf32(v.y); o.z = to_tf32(v.z); o.w = to_tf32(v.w);
    ((float4*)(g_w_t32 + (size_t)r * 512))[t] = o;
}

// ==================== compact + qkv combo ====================
__global__ __launch_bounds__(256)
void compact_qkv_kernel(const int* __restrict__ adj,
                        const float* __restrict__ queries, const float* __restrict__ keys,
                        const float* __restrict__ values,
                        const float* __restrict__ Wq, const float* __restrict__ bq,
                        const float* __restrict__ Wk, const float* __restrict__ bk,
                        const float* __restrict__ Wv, const float* __restrict__ bv)
{
    if (blockIdx.x < 512) {
        int j = blockIdx.x & 255, b = blockIdx.x >> 8, i = threadIdx.x;
        int lane = i & 31, w = i >> 5;
        bool keep = adj[((size_t)(b * Ll + i)) * Ll + j] != 1;
        unsigned m = __ballot_sync(0xffffffffu, keep);
        int wpos = __popc(m & ((1u << lane) - 1));
        __shared__ int wcnt[8], wbase[9];
        if (lane == 0) wcnt[w] = __popc(m);
        __syncthreads();
        if (i == 0) {
            int s = 0;
            for (int x = 0; x < 8; x++) { wbase[x] = s; s += wcnt[x]; }
            wbase[8] = atomicAdd(&g_cnt[b], s);
        }
        __syncthreads();
        if (keep) g_list[b * (Ll*Ll) + wbase[8] + wbase[w] + wpos] = (unsigned short)((j << 8) | i);
        return;
    }
    int bid2 = blockIdx.x - 512;
    int z = bid2 >> 6, rem = bid2 & 63;
    const float* X = (z == 0) ? queries : (z == 1) ? keys : values;
    const float* W = (z == 0) ? Wq : (z == 1) ? Wk : Wv;
    const float* bias = (z == 0) ? bq : (z == 1) ? bk : bv;
    float* Y = (z == 0) ? g_q : (z == 1) ? g_k : g_v;
    const float scale = (z == 0) ? QSCALE : 1.0f;

    __shared__ float Xs[16][64];
    __shared__ float Ws[16][64];
    int tid = threadIdx.x;
    int m0 = (rem >> 3) * 64, n0 = (rem & 7) * 64;
    int ty = tid >> 4, tx = tid & 15;
    int r = tid >> 2, c4 = tid & 3;
    float acc[4][4];
#pragma unroll
    for (int a = 0; a < 4; a++)
#pragma unroll
        for (int bb = 0; bb < 4; bb++) acc[a][bb] = 0.f;
    for (int kc = 0; kc < Ee; kc += 16) {
        float4 xv = *(const float4*)(X + (size_t)(m0 + r) * Ee + kc + c4 * 4);
        float4 wv = *(const float4*)(W + (size_t)(n0 + r) * Ee + kc + c4 * 4);
        __syncthreads();
        Xs[c4*4+0][r]=xv.x; Xs[c4*4+1][r]=xv.y; Xs[c4*4+2][r]=xv.z; Xs[c4*4+3][r]=xv.w;
        Ws[c4*4+0][r]=wv.x; Ws[c4*4+1][r]=wv.y; Ws[c4*4+2][r]=wv.z; Ws[c4*4+3][r]=wv.w;
        __syncthreads();
#pragma unroll
        for (int cc = 0; cc < 16; cc++) {
            float4 a = *(const float4*)&Xs[cc][ty*4];
            float4 bv4 = *(const float4*)&Ws[cc][tx*4];
            acc[0][0]+=a.x*bv4.x; acc[0][1]+=a.x*bv4.y; acc[0][2]+=a.x*bv4.z; acc[0][3]+=a.x*bv4.w;
            acc[1][0]+=a.y*bv4.x; acc[1][1]+=a.y*bv4.y; acc[1][2]+=a.y*bv4.z; acc[1][3]+=a.y*bv4.w;
            acc[2][0]+=a.z*bv4.x; acc[2][1]+=a.z*bv4.y; acc[2][2]+=a.z*bv4.z; acc[2][3]+=a.z*bv4.w;
            acc[3][0]+=a.w*bv4.x; acc[3][1]+=a.w*bv4.y; acc[3][2]+=a.w*bv4.z; acc[3][3]+=a.w*bv4.w;
        }
    }
#pragma unroll
    for (int rr = 0; rr < 4; rr++)
#pragma unroll
        for (int cc = 0; cc < 4; cc++)
            Y[(size_t)(m0+ty*4+rr) * Ee + n0+tx*4+cc] = (acc[rr][cc] + bias[n0+tx*4+cc]) * scale;
}

// Gather + tf32-round ONLY unmasked rel rows (compacted, list-ordered).
__global__ __launch_bounds__(256)
void split_rel_gather_kernel(const float* __restrict__ rel) {
    int b = blockIdx.y;
    int ent = blockIdx.x * 2 + (threadIdx.x >> 7);
    if (ent >= g_cnt[b]) return;
    int e = g_list[b * (Ll*Ll) + ent];
    int t = threadIdx.x & 127;
    float4 v = ((const float4*)(rel + ((size_t)(b * (Ll*Ll)) + e) * 512))[t];
    float4 o; o.x = to_tf32(v.x); o.y = to_tf32(v.y); o.z = to_tf32(v.z); o.w = to_tf32(v.w);
    ((float4*)(g_rel_t32 + ((size_t)(b * (Ll*Ll)) + ent) * 512))[t] = o;
}

// ==================== tf32 mma.sync relation attention ====================
// CTA = tile of 128 compacted pairs, 256 threads, occ 2.
// Single tf32 product (rne-prerounded). 128 kc-chunks of 32 fp32 (per head 16).
// Stage = A 16KB + B 16KB = 32KB; 3-deep ring (96KB), prefetch distance 2.
// cp.async issue for kc+2 is INTERLEAVED into the ks loop (2 per ks) so the
// LDGSTS issue cycles hide under the MMAs instead of preceding them.
#define KSTG 32768
#define MMA_SMEM (3*KSTG)        // 98304

__global__ void __launch_bounds__(256, 2) rel_attn_mma_kernel()
{
    extern __shared__ char smem[];
    const uint32_t sb = smem_u32(smem);
    const int tid = threadIdx.x, lane = tid & 31, w = tid >> 5;
    const int wm = w & 3, wn = w >> 2;
    const int t = blockIdx.x, b = blockIdx.y;

    const int cnt = g_cnt[b];
    if (t * 128 >= cnt) return;
    const size_t rbase = (size_t)(b * (Ll*Ll)) + t * 128;
    const unsigned short* lst = g_list + b * (Ll*Ll);

    float c[2][8][4];
#pragma unroll
    for (int mt = 0; mt < 2; mt++)
#pragma unroll
        for (int g = 0; g < 8; g++)
#pragma unroll
            for (int e = 0; e < 4; e++) c[mt][g][e] = 0.f;

    // full-chunk issue (pipeline warmup only)
    auto issue_full = [&](int kc) {
        const int h = kc >> 4;
        const int kcol = (kc & 15) * 32;
        const uint32_t st = sb + (kc % 3) * KSTG;
        const float* Bp = g_w_t32 + (size_t)h * 128 * 512;
#pragma unroll
        for (int r4 = 0; r4 < 4; r4++) {
            int idx = tid + r4 * 256;
            int row = idx >> 3, u = idx & 7;
            uint32_t so = SMEM_SWZ(row * 128 + u * 16);
            CP_ASYNC16(st + so,         g_rel_t32 + (rbase + row) * 512 + kcol + u * 4);
            CP_ASYNC16(st + 16384 + so, Bp + (size_t)row * 512 + kcol + u * 4);
        }
        CP_COMMIT();
    };

    issue_full(0); issue_full(1);

    for (int kc = 0; kc < 128; kc++) {
        const bool pf = (kc + 2 < 128);
        if (pf) { CP_WAIT1(); } else { CP_WAIT0(); }
        __syncthreads();

        // prefetch target (stage (kc+2)%3 was fully consumed before the sync)
        const int kp = kc + 2;
        const uint32_t stP = sb + (kp % 3) * KSTG;
        const float* ApP = g_rel_t32 + rbase * 512 + ((kp & 15) * 32);
        const float* BpP = g_w_t32 + (size_t)(kp >> 4) * 128 * 512 + ((kp & 15) * 32);

        const uint32_t stA = sb + (kc % 3) * KSTG;
        const uint32_t stB = stA + 16384;
        const int r8 = lane & 7, sel = lane >> 3;
#pragma unroll
        for (int ks = 0; ks < 4; ks++) {
            // interleaved prefetch: 2 cp.async lines per ks step
            if (pf) {
                int idx = tid + ks * 256;
                int row = idx >> 3, u = idx & 7;
                uint32_t so = SMEM_SWZ(row * 128 + u * 16);
                CP_ASYNC16(stP + so,         ApP + (size_t)row * 512 + u * 4);
                CP_ASYNC16(stP + 16384 + so, BpP + (size_t)row * 512 + u * 4);
            }
            // A fragments (tf32 via ldmatrix-b16 quadrant mapping)
            uint32_t a[2][4];
#pragma unroll
            for (int mt = 0; mt < 2; mt++) {
                int row = wm * 32 + mt * 16 + r8 + (sel & 1) * 8;
                int unit = ks * 2 + (sel >> 1);
                ldmx4(a[mt][0], a[mt][1], a[mt][2], a[mt][3],
                      stA + SMEM_SWZ(row * 128 + unit * 16));
            }
            // B fragments: one ldmx4 covers two n8-groups (b0,b1 each)
            uint32_t bq[4][2], bk[4][2];
#pragma unroll
            for (int pr = 0; pr < 2; pr++) {
                int rowq = wn * 32 + pr * 16 + r8 + (sel >> 1) * 8;
                int unit = ks * 2 + (sel & 1);
                ldmx4(bq[pr*2][0], bq[pr*2][1], bq[pr*2+1][0], bq[pr*2+1][1],
                      stB + SMEM_SWZ(rowq * 128 + unit * 16));
                int rowk = 64 + rowq;
                ldmx4(bk[pr*2][0], bk[pr*2][1], bk[pr*2+1][0], bk[pr*2+1][1],
                      stB + SMEM_SWZ(rowk * 128 + unit * 16));
            }
#pragma unroll
            for (int mt = 0; mt < 2; mt++)
#pragma unroll
                for (int g = 0; g < 4; g++) {
                    mma_tf32(c[mt][g],   a[mt], bq[g][0], bq[g][1]);
                    mma_tf32(c[mt][4+g], a[mt], bk[g][0], bk[g][1]);
                }
        }
        if (pf) CP_COMMIT();

        if ((kc & 15) == 15) {
            // -------- epilogue for head h; parr in the just-consumed stage --------
            const int h = kc >> 4;
            float* parr = (float*)(smem + (kc % 3) * KSTG);
#pragma unroll
            for (int mt = 0; mt < 2; mt++)
#pragma unroll
                for (int rh = 0; rh < 2; rh++) {
                    const int R = wm * 32 + mt * 16 + (lane >> 2) + rh * 8;
                    int gi = t * 128 + R;
                    const int e = lst[gi < cnt ? gi : cnt - 1];
                    const float* qrow = g_q + ((size_t)(b * Ll + (e & 255))) * Ee + h * 64;
                    const float* krow = g_k + ((size_t)(b * Ll + (e >> 8))) * Ee + h * 64;
                    float acc = 0.f;
#pragma unroll
                    for (int g = 0; g < 4; g++) {
                        const int d0 = wn * 32 + g * 8 + 2 * (lane & 3);
                        acc += (qrow[d0]     + c[mt][g][rh*2+0]) * (krow[d0]     + c[mt][4+g][rh*2+0]);
                        acc += (qrow[d0 + 1] + c[mt][g][rh*2+1]) * (krow[d0 + 1] + c[mt][4+g][rh*2+1]);
                    }
                    acc += __shfl_xor_sync(0xffffffffu, acc, 1);
                    acc += __shfl_xor_sync(0xffffffffu, acc, 2);
                    if ((lane & 3) == 0) parr[wn * 128 + R] = acc;
                }
            __syncthreads();
            if (tid < 128 && t * 128 + tid < cnt) {
                const int e = lst[t * 128 + tid];
                float lg = parr[tid] + parr[128 + tid];
                g_logits[((size_t)(b * Hh + h) * Ll + (e & 255)) * Ll + (e >> 8)] = lg;
            }
            __syncthreads();   // stage reused by cp.async next iteration
#pragma unroll
            for (int mt = 0; mt < 2; mt++)
#pragma unroll
                for (int g = 0; g < 8; g++)
#pragma unroll
                    for (int e2 = 0; e2 < 4; e2++) c[mt][g][e2] = 0.f;
        }
    }
}

// ==================== fused softmax + PV ====================
#define SPV_SMEM ((64*256 + 256*64) * 4)
__global__ __launch_bounds__(256, 1)
void softpv_kernel(const int* __restrict__ adj, float* __restrict__ out_attn)
{
    extern __shared__ float sm[];
    float* Ws = sm;
    float* Vs = sm + 64 * 256;
    int it = blockIdx.x, h = blockIdx.y, b = blockIdx.z;
    int i0 = it * 64;
    int tid = threadIdx.x, lane = tid & 31, w = tid >> 5;

    size_t lb = (((size_t)b * Hh + h) * Ll + i0) * Ll;
    const float4* lsrc = (const float4*)(g_logits + lb);
    float4* wdst = (float4*)Ws;
    for (int idx = tid; idx < 64 * 256 / 4; idx += 256) wdst[idx] = lsrc[idx];
    float4* vdst = (float4*)Vs;
    for (int idx = tid; idx < 256 * 64 / 4; idx += 256) {
        int jrow = idx >> 4, d4 = idx & 15;
        vdst[idx] = *(const float4*)(g_v + ((size_t)b * Ll + jrow) * Ee + h * 64 + d4 * 4);
    }
    __syncthreads();

    for (int r = w * 8; r < w * 8 + 8; r++) {
        int i = i0 + r;
        const int* arow = adj + ((size_t)(b * Ll + i)) * Ll;
        float v[8]; bool msk[8];
        float mx = -CUDART_INF_F;
#pragma unroll
        for (int u = 0; u < 8; u++) {
            int j = lane + u * 32;
            msk[u] = (arow[j] == 1);
            v[u] = msk[u] ? -CUDART_INF_F : Ws[r * 256 + j];
            mx = fmaxf(mx, v[u]);
        }
#pragma unroll
        for (int o = 16; o > 0; o >>= 1) mx = fmaxf(mx, __shfl_xor_sync(0xffffffffu, mx, o));
        float s = 0.f;
#pragma unroll
        for (int u = 0; u < 8; u++) {
            v[u] = msk[u] ? 0.f : expf(v[u] - mx);
            s += v[u];
        }
#pragma unroll
        for (int o = 16; o > 0; o >>= 1) s += __shfl_xor_sync(0xffffffffu, s, o);
        float inv = 1.0f / s;
#pragma unroll
        for (int u = 0; u < 8; u++) {
            int j = lane + u * 32;
            float wgt = v[u] * inv;
            Ws[r * 256 + j] = wgt;
            out_attn[(((size_t)b * Ll + i) * Ll + j) * Hh + h] = wgt;
        }
    }
    __syncthreads();

    int i = tid >> 2, tq = tid & 3;
    float acc[16];
#pragma unroll
    for (int dd = 0; dd < 16; dd++) acc[dd] = 0.f;
    const float* wrow = Ws + i * 256;
    for (int jj = 0; jj < 256; jj += 4) {
        float4 wv = *(const float4*)(wrow + jj);
#pragma unroll
        for (int u = 0; u < 4; u++) {
            float wsc = (u == 0) ? wv.x : (u == 1) ? wv.y : (u == 2) ? wv.z : wv.w;
            const float* vr = Vs + (jj + u) * 64 + tq * 16;
#pragma unroll
            for (int dd = 0; dd < 16; dd++) acc[dd] += wsc * vr[dd];
        }
    }
    float* op = g_o1 + ((size_t)b * Ll + i0 + i) * Ee + h * 64 + tq * 16;
#pragma unroll
    for (int dd = 0; dd < 16; dd++) op[dd] = acc[dd];
}

// ==================== output GEMM ====================
__global__ __launch_bounds__(256)
void gemm_bias_kernel(const float* __restrict__ X, const float* __restrict__ W,
                      const float* __restrict__ bias, float* __restrict__ Y,
                      int Mdim, int Ndim, int Kdim, float scale)
{
    __shared__ float Xs[16][64];
    __shared__ float Ws[16][64];
    int tid = threadIdx.x;
    int m0 = blockIdx.y * 64, n0 = blockIdx.x * 64;
    int ty = tid >> 4, tx = tid & 15;
    int r = tid >> 2, c4 = tid & 3;
    float acc[4][4];
#pragma unroll
    for (int a = 0; a < 4; a++)
#pragma unroll
        for (int bb = 0; bb < 4; bb++) acc[a][bb] = 0.f;
    for (int kc = 0; kc < Kdim; kc += 16) {
        float4 xv = *(const float4*)(X + (size_t)(m0 + r) * Kdim + kc + c4 * 4);
        float4 wv = *(const float4*)(W + (size_t)(n0 + r) * Kdim + kc + c4 * 4);
        __syncthreads();
        Xs[c4*4+0][r]=xv.x; Xs[c4*4+1][r]=xv.y; Xs[c4*4+2][r]=xv.z; Xs[c4*4+3][r]=xv.w;
        Ws[c4*4+0][r]=wv.x; Ws[c4*4+1][r]=wv.y; Ws[c4*4+2][r]=wv.z; Ws[c4*4+3][r]=wv.w;
        __syncthreads();
#pragma unroll
        for (int cc = 0; cc < 16; cc++) {
            float4 a = *(const float4*)&Xs[cc][ty*4];
            float4 bv4 = *(const float4*)&Ws[cc][tx*4];
            acc[0][0]+=a.x*bv4.x; acc[0][1]+=a.x*bv4.y; acc[0][2]+=a.x*bv4.z; acc[0][3]+=a.x*bv4.w;
            acc[1][0]+=a.y*bv4.x; acc[1][1]+=a.y*bv4.y; acc[1][2]+=a.y*bv4.z; acc[1][3]+=a.y*bv4.w;
            acc[2][0]+=a.z*bv4.x; acc[2][1]+=a.z*bv4.y; acc[2][2]+=a.z*bv4.z; acc[2][3]+=a.z*bv4.w;
            acc[3][0]+=a.w*bv4.x; acc[3][1]+=a.w*bv4.y; acc[3][2]+=a.w*bv4.z; acc[3][3]+=a.w*bv4.w;
        }
    }
#pragma unroll
    for (int rr = 0; rr < 4; rr++)
#pragma unroll
        for (int cc = 0; cc < 4; cc++)
            Y[(size_t)(m0+ty*4+rr) * Ndim + n0+tx*4+cc] = (acc[rr][cc] + bias[n0+tx*4+cc]) * scale;
}

// ---------------------------------------------------------------------------
extern "C" void kernel_launch(void* const* d_in, const int* in_sizes, int n_in,
                              void* d_out, int out_size)
{
    (void)in_sizes; (void)n_in; (void)out_size;
    const float* queries  = (const float*)d_in[0];
    const float* keys     = (const float*)d_in[1];
    const float* values   = (const float*)d_in[2];
    const float* relation = (const float*)d_in[3];
    const int*   adj      = (const int*)d_in[4];
    const float* Wq = (const float*)d_in[5];
    const float* bq = (const float*)d_in[6];
    const float* Wk = (const float*)d_in[7];
    const float* bk = (const float*)d_in[8];
    const float* Wv = (const float*)d_in[9];
    const float* bv = (const float*)d_in[10];
    const float* Wr = (const float*)d_in[11];
    const float* Wo = (const float*)d_in[12];
    const float* bo = (const float*)d_in[13];

    float* out      = (float*)d_out;
    float* out_attn = out + Bb * Ll * Ee;

    float *o1p;
    cudaGetSymbolAddress((void**)&o1p, g_o1);

    cudaFuncSetAttribute(rel_attn_mma_kernel, cudaFuncAttributeMaxDynamicSharedMemorySize, MMA_SMEM);
    cudaFuncSetAttribute(softpv_kernel, cudaFuncAttributeMaxDynamicSharedMemorySize, SPV_SMEM);

    split_w_kernel<<<1024, 128>>>(Wr);
    compact_qkv_kernel<<<704, 256>>>(adj, queries, keys, values,
                                     Wq, bq, Wk, bk, Wv, bv);
    split_rel_gather_kernel<<<dim3(Ll*Ll/2, Bb), 256>>>(relation);
    rel_attn_mma_kernel<<<dim3(512, Bb), 256, MMA_SMEM>>>();
    softpv_kernel<<<dim3(Ll / 64, Hh, Bb), 256, SPV_SMEM>>>(adj, out_attn);
    gemm_bias_kernel<<<dim3(Ee/64, (Bb*Ll)/64), 256>>>(o1p, Wo, bo, out, Bb*Ll, Ee, Ee, 1.0f);
}

// round 13
// speedup vs baseline: 2.0044x; 1.3938x over previous
#include <cuda_runtime.h>
#include <cuda_fp16.h>
#include <cstdint>
#include <math_constants.h>

#define Bb 2
#define Ll 256
#define Ee 512
#define Hh 8
#define QSCALE 0.125f

// ---------------- device scratch ----------------
__device__ float g_q[Bb*Ll*Ee];
__device__ float g_k[Bb*Ll*Ee];
__device__ float g_v[Bb*Ll*Ee];
__device__ float g_logits[(size_t)Bb*Hh*Ll*Ll];
__device__ float g_o1[Bb*Ll*Ee];
// fp16 (rne) copies; relation rows compacted in list order
__device__ __half g_rel_f16[(size_t)Bb*Ll*Ll*Ee];
__device__ __half g_w_f16[1024*512];   // [h*128+p][k]; p<64: Wrq rows, p>=64: Wrk rows
__device__ int g_cnt[Bb];
__device__ unsigned short g_list[Bb*Ll*Ll];

// ==================== PTX helpers ====================
__device__ __forceinline__ uint32_t smem_u32(const void* p) {
    uint32_t a;
    asm("{ .reg .u64 t; cvta.to.shared.u64 t, %1; cvt.u32.u64 %0, t; }" : "=r"(a) : "l"(p));
    return a;
}
#define SMEM_SWZ(o) ((o) ^ (((o) >> 3) & 0x70))
#define CP_ASYNC16(dst, src) \
    asm volatile("cp.async.cg.shared.global [%0], [%1], 16;" :: "r"(dst), "l"(src))
#define CP_COMMIT() asm volatile("cp.async.commit_group;" ::: "memory")
#define CP_WAIT1() asm volatile("cp.async.wait_group 1;" ::: "memory")
#define CP_WAIT0() asm volatile("cp.async.wait_group 0;" ::: "memory")

__device__ __forceinline__ void ldmx4(uint32_t& r0, uint32_t& r1, uint32_t& r2, uint32_t& r3, uint32_t addr) {
    asm volatile("ldmatrix.sync.aligned.m8n8.x4.shared.b16 {%0,%1,%2,%3}, [%4];"
        : "=r"(r0), "=r"(r1), "=r"(r2), "=r"(r3) : "r"(addr));
}
// m16n8k16 fp16 MMA, fp32 accumulate
__device__ __forceinline__ void mma_f16(float* c, const uint32_t* a, uint32_t b0, uint32_t b1) {
    asm volatile("mma.sync.aligned.m16n8k16.row.col.f32.f16.f16.f32 "
        "{%0,%1,%2,%3}, {%4,%5,%6,%7}, {%8,%9}, {%0,%1,%2,%3};"
        : "+f"(c[0]), "+f"(c[1]), "+f"(c[2]), "+f"(c[3])
        : "r"(a[0]), "r"(a[1]), "r"(a[2]), "r"(a[3]), "r"(b0), "r"(b1));
}

// ==================== split kernels (fp16 rne) ====================
__device__ __forceinline__ void cvt4_f16(float4 v, __half* dst) {
    __half2* d2 = (__half2*)dst;
    d2[0] = __floats2half2_rn(v.x, v.y);
    d2[1] = __floats2half2_rn(v.z, v.w);
}
__global__ void split_w_kernel(const float* __restrict__ Wr) {
    if (blockIdx.x == 0 && threadIdx.x < Bb) g_cnt[threadIdx.x] = 0;
    int r = blockIdx.x;                 // 0..1023
    int h = r >> 7, p = r & 127;
    int in_row = (p < 64) ? (h*64 + p) : (512 + h*64 + (p - 64));
    int t = threadIdx.x;                // 128 threads, 4 elems each
    float4 v = ((const float4*)(Wr + (size_t)in_row * 512))[t];
    cvt4_f16(v, g_w_f16 + (size_t)r * 512 + t * 4);
}

// ==================== compact + qkv combo ====================
__global__ __launch_bounds__(256)
void compact_qkv_kernel(const int* __restrict__ adj,
                        const float* __restrict__ queries, const float* __restrict__ keys,
                        const float* __restrict__ values,
                        const float* __restrict__ Wq, const float* __restrict__ bq,
                        const float* __restrict__ Wk, const float* __restrict__ bk,
                        const float* __restrict__ Wv, const float* __restrict__ bv)
{
    if (blockIdx.x < 512) {
        int j = blockIdx.x & 255, b = blockIdx.x >> 8, i = threadIdx.x;
        int lane = i & 31, w = i >> 5;
        bool keep = adj[((size_t)(b * Ll + i)) * Ll + j] != 1;
        unsigned m = __ballot_sync(0xffffffffu, keep);
        int wpos = __popc(m & ((1u << lane) - 1));
        __shared__ int wcnt[8], wbase[9];
        if (lane == 0) wcnt[w] = __popc(m);
        __syncthreads();
        if (i == 0) {
            int s = 0;
            for (int x = 0; x < 8; x++) { wbase[x] = s; s += wcnt[x]; }
            wbase[8] = atomicAdd(&g_cnt[b], s);
        }
        __syncthreads();
        if (keep) g_list[b * (Ll*Ll) + wbase[8] + wbase[w] + wpos] = (unsigned short)((j << 8) | i);
        return;
    }
    int bid2 = blockIdx.x - 512;
    int z = bid2 >> 6, rem = bid2 & 63;
    const float* X = (z == 0) ? queries : (z == 1) ? keys : values;
    const float* W = (z == 0) ? Wq : (z == 1) ? Wk : Wv;
    const float* bias = (z == 0) ? bq : (z == 1) ? bk : bv;
    float* Y = (z == 0) ? g_q : (z == 1) ? g_k : g_v;
    const float scale = (z == 0) ? QSCALE : 1.0f;

    __shared__ float Xs[16][64];
    __shared__ float Ws[16][64];
    int tid = threadIdx.x;
    int m0 = (rem >> 3) * 64, n0 = (rem & 7) * 64;
    int ty = tid >> 4, tx = tid & 15;
    int r = tid >> 2, c4 = tid & 3;
    float acc[4][4];
#pragma unroll
    for (int a = 0; a < 4; a++)
#pragma unroll
        for (int bb = 0; bb < 4; bb++) acc[a][bb] = 0.f;
    for (int kc = 0; kc < Ee; kc += 16) {
        float4 xv = *(const float4*)(X + (size_t)(m0 + r) * Ee + kc + c4 * 4);
        float4 wv = *(const float4*)(W + (size_t)(n0 + r) * Ee + kc + c4 * 4);
        __syncthreads();
        Xs[c4*4+0][r]=xv.x; Xs[c4*4+1][r]=xv.y; Xs[c4*4+2][r]=xv.z; Xs[c4*4+3][r]=xv.w;
        Ws[c4*4+0][r]=wv.x; Ws[c4*4+1][r]=wv.y; Ws[c4*4+2][r]=wv.z; Ws[c4*4+3][r]=wv.w;
        __syncthreads();
#pragma unroll
        for (int cc = 0; cc < 16; cc++) {
            float4 a = *(const float4*)&Xs[cc][ty*4];
            float4 bv4 = *(const float4*)&Ws[cc][tx*4];
            acc[0][0]+=a.x*bv4.x; acc[0][1]+=a.x*bv4.y; acc[0][2]+=a.x*bv4.z; acc[0][3]+=a.x*bv4.w;
            acc[1][0]+=a.y*bv4.x; acc[1][1]+=a.y*bv4.y; acc[1][2]+=a.y*bv4.z; acc[1][3]+=a.y*bv4.w;
            acc[2][0]+=a.z*bv4.x; acc[2][1]+=a.z*bv4.y; acc[2][2]+=a.z*bv4.z; acc[2][3]+=a.z*bv4.w;
            acc[3][0]+=a.w*bv4.x; acc[3][1]+=a.w*bv4.y; acc[3][2]+=a.w*bv4.z; acc[3][3]+=a.w*bv4.w;
        }
    }
#pragma unroll
    for (int rr = 0; rr < 4; rr++)
#pragma unroll
        for (int cc = 0; cc < 4; cc++)
            Y[(size_t)(m0+ty*4+rr) * Ee + n0+tx*4+cc] = (acc[rr][cc] + bias[n0+tx*4+cc]) * scale;
}

// Gather + fp16-round ONLY unmasked rel rows (compacted, list-ordered).
__global__ __launch_bounds__(256)
void split_rel_gather_kernel(const float* __restrict__ rel) {
    int b = blockIdx.y;
    int ent = blockIdx.x * 2 + (threadIdx.x >> 7);
    if (ent >= g_cnt[b]) return;
    int e = g_list[b * (Ll*Ll) + ent];
    int t = threadIdx.x & 127;
    float4 v = ((const float4*)(rel + ((size_t)(b * (Ll*Ll)) + e) * 512))[t];
    cvt4_f16(v, g_rel_f16 + ((size_t)(b * (Ll*Ll)) + ent) * 512 + t * 4);
}

// ==================== fp16 mma.sync relation attention ====================
// CTA = tile of 128 compacted pairs, 256 threads, occ 2.
// Single fp16 product (rne-prerounded; 10-bit mantissa == tf32).
// 64 kc-chunks of 64 halves (8 per head). Stage = A 16KB + B 16KB = 32KB;
// 3-deep ring (96KB), prefetch distance 2, cp.async interleaved into ks loop.
// Per ks (k=16): 2 A ldmatrix + 4 B ldmatrix -> 16 MMA (m16n8k16).
#define KSTG 32768
#define MMA_SMEM (3*KSTG)        // 98304

__global__ void __launch_bounds__(256, 2) rel_attn_mma_kernel()
{
    extern __shared__ char smem[];
    const uint32_t sb = smem_u32(smem);
    const int tid = threadIdx.x, lane = tid & 31, w = tid >> 5;
    const int wm = w & 3, wn = w >> 2;
    const int t = blockIdx.x, b = blockIdx.y;

    const int cnt = g_cnt[b];
    if (t * 128 >= cnt) return;
    const size_t rbase = (size_t)(b * (Ll*Ll)) + t * 128;
    const unsigned short* lst = g_list + b * (Ll*Ll);

    float c[2][8][4];
#pragma unroll
    for (int mt = 0; mt < 2; mt++)
#pragma unroll
        for (int g = 0; g < 8; g++)
#pragma unroll
            for (int e = 0; e < 4; e++) c[mt][g][e] = 0.f;

    // full-chunk issue (pipeline warmup only)
    auto issue_full = [&](int kc) {
        const int h = kc >> 3;
        const int kcol = (kc & 7) * 64;
        const uint32_t st = sb + (kc % 3) * KSTG;
        const __half* Bp = g_w_f16 + (size_t)h * 128 * 512;
#pragma unroll
        for (int r4 = 0; r4 < 4; r4++) {
            int idx = tid + r4 * 256;       // 1024 16B units each of A and B
            int row = idx >> 3, u = idx & 7;
            uint32_t so = SMEM_SWZ(row * 128 + u * 16);
            CP_ASYNC16(st + so,         g_rel_f16 + (rbase + row) * 512 + kcol + u * 8);
            CP_ASYNC16(st + 16384 + so, Bp + (size_t)row * 512 + kcol + u * 8);
        }
        CP_COMMIT();
    };

    issue_full(0); issue_full(1);

    for (int kc = 0; kc < 64; kc++) {
        const bool pf = (kc + 2 < 64);
        if (pf) { CP_WAIT1(); } else { CP_WAIT0(); }
        __syncthreads();

        // prefetch target (stage (kc+2)%3 was fully consumed before the sync)
        const int kp = kc + 2;
        const uint32_t stP = sb + (kp % 3) * KSTG;
        const __half* ApP = g_rel_f16 + rbase * 512 + ((kp & 7) * 64);
        const __half* BpP = g_w_f16 + (size_t)(kp >> 3) * 128 * 512 + ((kp & 7) * 64);

        const uint32_t stA = sb + (kc % 3) * KSTG;
        const uint32_t stB = stA + 16384;
        const int r8 = lane & 7, sel = lane >> 3;
#pragma unroll
        for (int ks = 0; ks < 4; ks++) {
            // interleaved prefetch: 2 cp.async lines per ks step
            if (pf) {
                int idx = tid + ks * 256;
                int row = idx >> 3, u = idx & 7;
                uint32_t so = SMEM_SWZ(row * 128 + u * 16);
                CP_ASYNC16(stP + so,         ApP + (size_t)row * 512 + u * 8);
                CP_ASYNC16(stP + 16384 + so, BpP + (size_t)row * 512 + u * 8);
            }
            // A fragments: m16 x k16
            uint32_t a[2][4];
#pragma unroll
            for (int mt = 0; mt < 2; mt++) {
                int row = wm * 32 + mt * 16 + r8 + (sel & 1) * 8;
                int c16 = ks * 2 + (sel >> 1);
                ldmx4(a[mt][0], a[mt][1], a[mt][2], a[mt][3],
                      stA + SMEM_SWZ(row * 128 + c16 * 16));
            }
            // B fragments: 4 ldmx4 -> bq[4][2], bk[4][2]
            uint32_t bq[4][2], bk[4][2];
#pragma unroll
            for (int gp = 0; gp < 2; gp++) {
                int c16 = ks * 2 + (sel & 1);
                int rowq = wn * 32 + gp * 16 + r8 + (sel >> 1) * 8;
                ldmx4(bq[gp*2][0], bq[gp*2][1], bq[gp*2+1][0], bq[gp*2+1][1],
                      stB + SMEM_SWZ(rowq * 128 + c16 * 16));
                int rowk = 64 + rowq;
                ldmx4(bk[gp*2][0], bk[gp*2][1], bk[gp*2+1][0], bk[gp*2+1][1],
                      stB + SMEM_SWZ(rowk * 128 + c16 * 16));
            }
#pragma unroll
            for (int mt = 0; mt < 2; mt++)
#pragma unroll
                for (int g = 0; g < 4; g++) {
                    mma_f16(c[mt][g],   a[mt], bq[g][0], bq[g][1]);
                    mma_f16(c[mt][4+g], a[mt], bk[g][0], bk[g][1]);
                }
        }
        if (pf) CP_COMMIT();

        if ((kc & 7) == 7) {
            // -------- epilogue for head h; parr in the just-consumed stage --------
            const int h = kc >> 3;
            float* parr = (float*)(smem + (kc % 3) * KSTG);
#pragma unroll
            for (int mt = 0; mt < 2; mt++)
#pragma unroll
                for (int rh = 0; rh < 2; rh++) {
                    const int R = wm * 32 + mt * 16 + (lane >> 2) + rh * 8;
                    int gi = t * 128 + R;
                    const int e = lst[gi < cnt ? gi : cnt - 1];
                    const float* qrow = g_q + ((size_t)(b * Ll + (e & 255))) * Ee + h * 64;
                    const float* krow = g_k + ((size_t)(b * Ll + (e >> 8))) * Ee + h * 64;
                    float acc = 0.f;
#pragma unroll
                    for (int g = 0; g < 4; g++) {
                        const int d0 = wn * 32 + g * 8 + 2 * (lane & 3);
                        acc += (qrow[d0]     + c[mt][g][rh*2+0]) * (krow[d0]     + c[mt][4+g][rh*2+0]);
                        acc += (qrow[d0 + 1] + c[mt][g][rh*2+1]) * (krow[d0 + 1] + c[mt][4+g][rh*2+1]);
                    }
                    acc += __shfl_xor_sync(0xffffffffu, acc, 1);
                    acc += __shfl_xor_sync(0xffffffffu, acc, 2);
                    if ((lane & 3) == 0) parr[wn * 128 + R] = acc;
                }
            __syncthreads();
            if (tid < 128 && t * 128 + tid < cnt) {
                const int e = lst[t * 128 + tid];
                float lg = parr[tid] + parr[128 + tid];
                g_logits[((size_t)(b * Hh + h) * Ll + (e & 255)) * Ll + (e >> 8)] = lg;
            }
            __syncthreads();   // stage reused by cp.async next iteration
#pragma unroll
            for (int mt = 0; mt < 2; mt++)
#pragma unroll
                for (int g = 0; g < 8; g++)
#pragma unroll
                    for (int e2 = 0; e2 < 4; e2++) c[mt][g][e2] = 0.f;
        }
    }
}

// ==================== fused softmax + PV ====================
#define SPV_SMEM ((64*256 + 256*64) * 4)
__global__ __launch_bounds__(256, 1)
void softpv_kernel(const int* __restrict__ adj, float* __restrict__ out_attn)
{
    extern __shared__ float sm[];
    float* Ws = sm;
    float* Vs = sm + 64 * 256;
    int it = blockIdx.x, h = blockIdx.y, b = blockIdx.z;
    int i0 = it * 64;
    int tid = threadIdx.x, lane = tid & 31, w = tid >> 5;

    size_t lb = (((size_t)b * Hh + h) * Ll + i0) * Ll;
    const float4* lsrc = (const float4*)(g_logits + lb);
    float4* wdst = (float4*)Ws;
    for (int idx = tid; idx < 64 * 256 / 4; idx += 256) wdst[idx] = lsrc[idx];
    float4* vdst = (float4*)Vs;
    for (int idx = tid; idx < 256 * 64 / 4; idx += 256) {
        int jrow = idx >> 4, d4 = idx & 15;
        vdst[idx] = *(const float4*)(g_v + ((size_t)b * Ll + jrow) * Ee + h * 64 + d4 * 4);
    }
    __syncthreads();

    for (int r = w * 8; r < w * 8 + 8; r++) {
        int i = i0 + r;
        const int* arow = adj + ((size_t)(b * Ll + i)) * Ll;
        float v[8]; bool msk[8];
        float mx = -CUDART_INF_F;
#pragma unroll
        for (int u = 0; u < 8; u++) {
            int j = lane + u * 32;
            msk[u] = (arow[j] == 1);
            v[u] = msk[u] ? -CUDART_INF_F : Ws[r * 256 + j];
            mx = fmaxf(mx, v[u]);
        }
#pragma unroll
        for (int o = 16; o > 0; o >>= 1) mx = fmaxf(mx, __shfl_xor_sync(0xffffffffu, mx, o));
        float s = 0.f;
#pragma unroll
        for (int u = 0; u < 8; u++) {
            v[u] = msk[u] ? 0.f : expf(v[u] - mx);
            s += v[u];
        }
#pragma unroll
        for (int o = 16; o > 0; o >>= 1) s += __shfl_xor_sync(0xffffffffu, s, o);
        float inv = 1.0f / s;
#pragma unroll
        for (int u = 0; u < 8; u++) {
            int j = lane + u * 32;
            float wgt = v[u] * inv;
            Ws[r * 256 + j] = wgt;
            out_attn[(((size_t)b * Ll + i) * Ll + j) * Hh + h] = wgt;
        }
    }
    __syncthreads();

    int i = tid >> 2, tq = tid & 3;
    float acc[16];
#pragma unroll
    for (int dd = 0; dd < 16; dd++) acc[dd] = 0.f;
    const float* wrow = Ws + i * 256;
    for (int jj = 0; jj < 256; jj += 4) {
        float4 wv = *(const float4*)(wrow + jj);
#pragma unroll
        for (int u = 0; u < 4; u++) {
            float wsc = (u == 0) ? wv.x : (u == 1) ? wv.y : (u == 2) ? wv.z : wv.w;
            const float* vr = Vs + (jj + u) * 64 + tq * 16;
#pragma unroll
            for (int dd = 0; dd < 16; dd++) acc[dd] += wsc * vr[dd];
        }
    }
    float* op = g_o1 + ((size_t)b * Ll + i0 + i) * Ee + h * 64 + tq * 16;
#pragma unroll
    for (int dd = 0; dd < 16; dd++) op[dd] = acc[dd];
}

// ==================== output GEMM ====================
__global__ __launch_bounds__(256)
void gemm_bias_kernel(const float* __restrict__ X, const float* __restrict__ W,
                      const float* __restrict__ bias, float* __restrict__ Y,
                      int Mdim, int Ndim, int Kdim, float scale)
{
    __shared__ float Xs[16][64];
    __shared__ float Ws[16][64];
    int tid = threadIdx.x;
    int m0 = blockIdx.y * 64, n0 = blockIdx.x * 64;
    int ty = tid >> 4, tx = tid & 15;
    int r = tid >> 2, c4 = tid & 3;
    float acc[4][4];
#pragma unroll
    for (int a = 0; a < 4; a++)
#pragma unroll
        for (int bb = 0; bb < 4; bb++) acc[a][bb] = 0.f;
    for (int kc = 0; kc < Kdim; kc += 16) {
        float4 xv = *(const float4*)(X + (size_t)(m0 + r) * Kdim + kc + c4 * 4);
        float4 wv = *(const float4*)(W + (size_t)(n0 + r) * Kdim + kc + c4 * 4);
        __syncthreads();
        Xs[c4*4+0][r]=xv.x; Xs[c4*4+1][r]=xv.y; Xs[c4*4+2][r]=xv.z; Xs[c4*4+3][r]=xv.w;
        Ws[c4*4+0][r]=wv.x; Ws[c4*4+1][r]=wv.y; Ws[c4*4+2][r]=wv.z; Ws[c4*4+3][r]=wv.w;
        __syncthreads();
#pragma unroll
        for (int cc = 0; cc < 16; cc++) {
            float4 a = *(const float4*)&Xs[cc][ty*4];
            float4 bv4 = *(const float4*)&Ws[cc][tx*4];
            acc[0][0]+=a.x*bv4.x; acc[0][1]+=a.x*bv4.y; acc[0][2]+=a.x*bv4.z; acc[0][3]+=a.x*bv4.w;
            acc[1][0]+=a.y*bv4.x; acc[1][1]+=a.y*bv4.y; acc[1][2]+=a.y*bv4.z; acc[1][3]+=a.y*bv4.w;
            acc[2][0]+=a.z*bv4.x; acc[2][1]+=a.z*bv4.y; acc[2][2]+=a.z*bv4.z; acc[2][3]+=a.z*bv4.w;
            acc[3][0]+=a.w*bv4.x; acc[3][1]+=a.w*bv4.y; acc[3][2]+=a.w*bv4.z; acc[3][3]+=a.w*bv4.w;
        }
    }
#pragma unroll
    for (int rr = 0; rr < 4; rr++)
#pragma unroll
        for (int cc = 0; cc < 4; cc++)
            Y[(size_t)(m0+ty*4+rr) * Ndim + n0+tx*4+cc] = (acc[rr][cc] + bias[n0+tx*4+cc]) * scale;
}

// ---------------------------------------------------------------------------
extern "C" void kernel_launch(void* const* d_in, const int* in_sizes, int n_in,
                              void* d_out, int out_size)
{
    (void)in_sizes; (void)n_in; (void)out_size;
    const float* queries  = (const float*)d_in[0];
    const float* keys     = (const float*)d_in[1];
    const float* values   = (const float*)d_in[2];
    const float* relation = (const float*)d_in[3];
    const int*   adj      = (const int*)d_in[4];
    const float* Wq = (const float*)d_in[5];
    const float* bq = (const float*)d_in[6];
    const float* Wk = (const float*)d_in[7];
    const float* bk = (const float*)d_in[8];
    const float* Wv = (const float*)d_in[9];
    const float* bv = (const float*)d_in[10];
    const float* Wr = (const float*)d_in[11];
    const float* Wo = (const float*)d_in[12];
    const float* bo = (const float*)d_in[13];

    float* out      = (float*)d_out;
    float* out_attn = out + Bb * Ll * Ee;

    float *o1p;
    cudaGetSymbolAddress((void**)&o1p, g_o1);

    cudaFuncSetAttribute(rel_attn_mma_kernel, cudaFuncAttributeMaxDynamicSharedMemorySize, MMA_SMEM);
    cudaFuncSetAttribute(softpv_kernel, cudaFuncAttributeMaxDynamicSharedMemorySize, SPV_SMEM);

    split_w_kernel<<<1024, 128>>>(Wr);
    compact_qkv_kernel<<<704, 256>>>(adj, queries, keys, values,
                                     Wq, bq, Wk, bk, Wv, bv);
    split_rel_gather_kernel<<<dim3(Ll*Ll/2, Bb), 256>>>(relation);
    rel_attn_mma_kernel<<<dim3(512, Bb), 256, MMA_SMEM>>>();
    softpv_kernel<<<dim3(Ll / 64, Hh, Bb), 256, SPV_SMEM>>>(adj, out_attn);
    gemm_bias_kernel<<<dim3(Ee/64, (Bb*Ll)/64), 256>>>(o1p, Wo, bo, out, Bb*Ll, Ee, Ee, 1.0f);
}